// round 1
// baseline (speedup 1.0000x reference)
#include <cuda_runtime.h>
#include <math.h>

// dims
#define N_  16
#define C_  32
#define V_  2048
#define VC_ 256
#define S_  64
#define L_  12
#define CO_ 32
#define NL_ 192        // N_*L_
#define M_  6144       // C_*N_*L_  (column index m = c*192 + n*12 + l)

// residual fusion scales
#define N1F 0.8f
#define N2F 0.2f
#define N3F 0.2f
#define N4F 0.2f

// ---------------- scratch (static device arrays; no allocs allowed) ----------------
__device__ float g_X  [V_  * M_];
__device__ float g_Z2 [V_  * M_];
__device__ float g_Z3 [V_  * M_];
__device__ float g_HF [V_  * M_];
__device__ float g_Xc [VC_ * M_];
__device__ float g_Zc2[VC_ * M_];
__device__ float g_Zc3[VC_ * M_];
__device__ float g_HC [VC_ * M_];
__device__ float g_Sxg[S_  * M_];
__device__ float g_Zs2[S_  * M_];
__device__ float g_Zs3[S_  * M_];
__device__ float g_HS [S_  * M_];
__device__ float g_asmat[S_ * S_];
__device__ float g_sup0 [S_ * S_];
__device__ float g_sup1 [S_ * S_];
__device__ float g_acsT [S_ * VC_];   // acsT[s][w] = acs[w][s]
__device__ float g_afcT [VC_ * V_];   // afcT[w][v] = afc[v][w]

// ---------------- transpose x [N,C,V,L] -> X [V, M] ----------------
__global__ void transpose_in(const float* __restrict__ x) {
    int idx = blockIdx.x * blockDim.x + threadIdx.x;
    if (idx >= N_ * C_ * V_ * L_) return;
    int l = idx % L_;
    int v = (idx / L_) % V_;
    int c = (idx / (L_ * V_)) % C_;
    int n = idx / (L_ * V_ * C_);
    g_X[(size_t)v * M_ + c * NL_ + n * L_ + l] = x[idx];
}

__global__ void transpose_acs(const float* __restrict__ acs) {
    int idx = blockIdx.x * blockDim.x + threadIdx.x;
    if (idx >= S_ * VC_) return;
    int s = idx / VC_, w = idx % VC_;
    g_acsT[idx] = acs[w * S_ + s];
}

__global__ void transpose_afc(const float* __restrict__ afc) {
    int idx = blockIdx.x * blockDim.x + threadIdx.x;
    if (idx >= VC_ * V_) return;
    int w = idx / V_, v = idx % V_;
    g_afcT[idx] = afc[(size_t)v * VC_ + w];
}

// ---------------- channel mix: H = b + W1*Xin, Z2 = W2*Xin, Z3 = W3*Xin ----------------
// Xin layout [R, M] (per row: [C, NL]); one block per node row, 192 threads (one per nl).
__global__ void chanmix(const float* __restrict__ Xin,
                        const float* __restrict__ W,   // [32, 96]
                        const float* __restrict__ b,   // [32]
                        float* __restrict__ H,
                        float* __restrict__ Z2,
                        float* __restrict__ Z3) {
    __shared__ float sX[M_];      // 24 KB
    __shared__ float sW[32 * 96]; // 12 KB
    __shared__ float sb[32];
    int r = blockIdx.x;
    const float* xr = Xin + (size_t)r * M_;
    for (int i = threadIdx.x; i < M_; i += 192)      sX[i] = xr[i];
    for (int i = threadIdx.x; i < 32 * 96; i += 192) sW[i] = W[i];
    if (threadIdx.x < 32) sb[threadIdx.x] = b[threadIdx.x];
    __syncthreads();

    int nl = threadIdx.x;  // 0..191
    float xv[32];
    #pragma unroll
    for (int c = 0; c < 32; c++) xv[c] = sX[c * NL_ + nl];

    for (int o = 0; o < 32; o++) {
        const float* wr = &sW[o * 96];
        float a0 = sb[o], a1 = 0.f, a2 = 0.f;
        #pragma unroll
        for (int c = 0; c < 32; c++) {
            float xc = xv[c];
            a0 = fmaf(wr[c],      xc, a0);
            a1 = fmaf(wr[32 + c], xc, a1);
            a2 = fmaf(wr[64 + c], xc, a2);
        }
        size_t base = (size_t)r * M_ + o * NL_ + nl;
        H[base]  = a0;
        Z2[base] = a1;
        Z3[base] = a2;
    }
}

// ---------------- TN SGEMM: C[mo,mn] (op) sum_k A[k,mo] * B[k,mn] ----------------
// A: [K x Mo] (k-major), B: [K x Mn] (k-major), C: [Mo x Mn]
// mode 0: C = acc;  mode 1: C += acc;  mode 2: C += alpha * relu(acc)
__global__ void __launch_bounds__(256)
sgemm_tn(const float* __restrict__ A, const float* __restrict__ B, float* __restrict__ C,
         int Mo, int Mn, int K, int mode, float alpha) {
    __shared__ float As[16][128];
    __shared__ float Bs[16][128];
    const int bm = blockIdx.y * 128;
    const int bn = blockIdx.x * 128;
    const int tid = threadIdx.x;
    const int tx = tid & 15;
    const int ty = tid >> 4;
    const int lk = tid >> 5;         // 0..7
    const int lm = (tid & 31) << 2;  // 0,4,...,124

    float acc[8][8];
    #pragma unroll
    for (int i = 0; i < 8; i++)
        #pragma unroll
        for (int j = 0; j < 8; j++) acc[i][j] = 0.f;

    for (int k0 = 0; k0 < K; k0 += 16) {
        #pragma unroll
        for (int kk = 0; kk < 2; kk++) {
            int kr = k0 + lk + kk * 8;
            int mc = bm + lm;
            float4 va = make_float4(0.f, 0.f, 0.f, 0.f);
            if (mc < Mo) va = *reinterpret_cast<const float4*>(A + (size_t)kr * Mo + mc);
            As[lk + kk * 8][lm + 0] = va.x;
            As[lk + kk * 8][lm + 1] = va.y;
            As[lk + kk * 8][lm + 2] = va.z;
            As[lk + kk * 8][lm + 3] = va.w;
            float4 vb = *reinterpret_cast<const float4*>(B + (size_t)kr * Mn + bn + lm);
            Bs[lk + kk * 8][lm + 0] = vb.x;
            Bs[lk + kk * 8][lm + 1] = vb.y;
            Bs[lk + kk * 8][lm + 2] = vb.z;
            Bs[lk + kk * 8][lm + 3] = vb.w;
        }
        __syncthreads();
        #pragma unroll
        for (int k = 0; k < 16; k++) {
            float4 a0 = *reinterpret_cast<const float4*>(&As[k][ty * 8]);
            float4 a1 = *reinterpret_cast<const float4*>(&As[k][ty * 8 + 4]);
            float4 b0 = *reinterpret_cast<const float4*>(&Bs[k][tx * 8]);
            float4 b1 = *reinterpret_cast<const float4*>(&Bs[k][tx * 8 + 4]);
            float a[8] = {a0.x, a0.y, a0.z, a0.w, a1.x, a1.y, a1.z, a1.w};
            float bb[8] = {b0.x, b0.y, b0.z, b0.w, b1.x, b1.y, b1.z, b1.w};
            #pragma unroll
            for (int i = 0; i < 8; i++)
                #pragma unroll
                for (int j = 0; j < 8; j++)
                    acc[i][j] = fmaf(a[i], bb[j], acc[i][j]);
        }
        __syncthreads();
    }

    #pragma unroll
    for (int i = 0; i < 8; i++) {
        int row = bm + ty * 8 + i;
        if (row >= Mo) continue;
        float* cp = C + (size_t)row * Mn + bn + tx * 8;
        #pragma unroll
        for (int jj = 0; jj < 2; jj++) {
            float x0 = acc[i][jj * 4 + 0], x1 = acc[i][jj * 4 + 1];
            float x2 = acc[i][jj * 4 + 2], x3 = acc[i][jj * 4 + 3];
            float4 r;
            if (mode == 0) {
                r = make_float4(x0, x1, x2, x3);
            } else {
                float4 p = *reinterpret_cast<const float4*>(cp + jj * 4);
                if (mode == 1) {
                    r = make_float4(p.x + x0, p.y + x1, p.z + x2, p.w + x3);
                } else {
                    r = make_float4(p.x + alpha * fmaxf(x0, 0.f),
                                    p.y + alpha * fmaxf(x1, 0.f),
                                    p.z + alpha * fmaxf(x2, 0.f),
                                    p.w + alpha * fmaxf(x3, 0.f));
                }
            }
            *reinterpret_cast<float4*>(cp + jj * 4) = r;
        }
    }
}

// ---------------- as_mat[s,t] = relu(sum_j Sxg[s,j]*Sxg[t,perm(j)] - 0.5) ----------------
// perm(j): j interpreted as (l',n',c') row-major -> column index c'*192 + n'*12 + l'
__global__ void asmat_kernel() {
    __shared__ float Ps[M_];  // 24 KB
    int s = blockIdx.x;
    for (int i = threadIdx.x; i < M_; i += blockDim.x)
        Ps[i] = g_Sxg[(size_t)s * M_ + i];
    __syncthreads();
    int warp = threadIdx.x >> 5, lane = threadIdx.x & 31;
    for (int t = warp; t < S_; t += 8) {
        float acc = 0.f;
        const float* qt = &g_Sxg[(size_t)t * M_];
        for (int j = lane; j < M_; j += 32) {
            int cp = j & 31;
            int np = (j >> 5) & 15;
            int lp = j >> 9;
            int pj = cp * NL_ + np * L_ + lp;
            acc = fmaf(Ps[j], qt[pj], acc);
        }
        #pragma unroll
        for (int o = 16; o > 0; o >>= 1) acc += __shfl_down_sync(0xffffffffu, acc, o);
        if (lane == 0) {
            float v = acc - 0.5f;
            g_asmat[s * S_ + t] = v > 0.f ? v : 0.f;
        }
    }
}

// ---------------- sup0 = softmax(rownorm(as_mat)), sup1 = softmax(rownorm(as_mat^T)) -----
__global__ void supmat_kernel() {
    __shared__ float Ms[S_ * S_];
    int t = threadIdx.x;
    for (int i = t; i < S_ * S_; i += blockDim.x) Ms[i] = g_asmat[i];
    __syncthreads();
    if (t >= S_) return;
    float vals[S_];
    // sup0: row t of row-normalized as_mat, then softmax
    {
        float rs = 0.f;
        for (int u = 0; u < S_; u++) rs += Ms[t * S_ + u];
        float dinv = rs > 0.f ? 1.f / rs : 0.f;
        float mx = -1e30f;
        for (int u = 0; u < S_; u++) { vals[u] = Ms[t * S_ + u] * dinv; mx = fmaxf(mx, vals[u]); }
        float se = 0.f;
        for (int u = 0; u < S_; u++) { vals[u] = expf(vals[u] - mx); se += vals[u]; }
        float inv = 1.f / se;
        for (int u = 0; u < S_; u++) g_sup0[t * S_ + u] = vals[u] * inv;
    }
    // sup1: row t of row-normalized as_mat^T (i.e. column t, scaled by 1/colsum_t), softmax
    {
        float cs = 0.f;
        for (int u = 0; u < S_; u++) cs += Ms[u * S_ + t];
        float dinv = cs > 0.f ? 1.f / cs : 0.f;
        float mx = -1e30f;
        for (int u = 0; u < S_; u++) { vals[u] = Ms[u * S_ + t] * dinv; mx = fmaxf(mx, vals[u]); }
        float se = 0.f;
        for (int u = 0; u < S_; u++) { vals[u] = expf(vals[u] - mx); se += vals[u]; }
        float inv = 1.f / se;
        for (int u = 0; u < S_; u++) g_sup1[t * S_ + u] = vals[u] * inv;
    }
}

// ---------------- write outputs: hf [N,CO,V,L], hc [N,CO,VC,L], hs [N,CO,S,L] ----------------
__global__ void transpose_out(float* __restrict__ out) {
    const int HFsz = N_ * CO_ * V_ * L_;   // 12582912
    const int HCsz = N_ * CO_ * VC_ * L_;  // 1572864
    const int HSsz = N_ * CO_ * S_ * L_;   // 393216
    int idx = blockIdx.x * blockDim.x + threadIdx.x;
    if (idx < HFsz) {
        int l = idx % L_;
        int v = (idx / L_) % V_;
        int o = (idx / (L_ * V_)) % CO_;
        int n = idx / (L_ * V_ * CO_);
        out[idx] = g_HF[(size_t)v * M_ + o * NL_ + n * L_ + l];
    } else if (idx < HFsz + HCsz) {
        int k = idx - HFsz;
        int l = k % L_;
        int w = (k / L_) % VC_;
        int o = (k / (L_ * VC_)) % CO_;
        int n = k / (L_ * VC_ * CO_);
        out[idx] = g_HC[(size_t)w * M_ + o * NL_ + n * L_ + l];
    } else if (idx < HFsz + HCsz + HSsz) {
        int k = idx - HFsz - HCsz;
        int l = k % L_;
        int s = (k / L_) % S_;
        int o = (k / (L_ * S_)) % CO_;
        int n = k / (L_ * S_ * CO_);
        out[idx] = g_HS[(size_t)s * M_ + o * NL_ + n * L_ + l];
    }
}

// ---------------- host side ----------------
static inline void launch_gemm(const void* A, const void* B, void* C,
                               int Mo, int K, int mode, float alpha) {
    dim3 grid(M_ / 128, (Mo + 127) / 128);
    sgemm_tn<<<grid, 256>>>((const float*)A, (const float*)B, (float*)C,
                            Mo, M_, K, mode, alpha);
}

extern "C" void kernel_launch(void* const* d_in, const int* in_sizes, int n_in,
                              void* d_out, int out_size) {
    (void)in_sizes; (void)n_in; (void)out_size;
    const float* x         = (const float*)d_in[0];
    const float* support   = (const float*)d_in[1];  // [2, V, V]
    const float* support_c = (const float*)d_in[2];  // [2, VC, VC]
    const float* acs       = (const float*)d_in[3];  // [VC, S]
    const float* afc       = (const float*)d_in[4];  // [V, VC]
    const float* W         = (const float*)d_in[5];  // [CO, 3C]
    const float* b         = (const float*)d_in[6];  // [CO]
    float* out = (float*)d_out;

    void *pX, *pZ2, *pZ3, *pHF, *pXc, *pZc2, *pZc3, *pHC;
    void *pSxg, *pZs2, *pZs3, *pHS, *psup0, *psup1, *pacsT, *pafcT;
    cudaGetSymbolAddress(&pX, g_X);     cudaGetSymbolAddress(&pZ2, g_Z2);
    cudaGetSymbolAddress(&pZ3, g_Z3);   cudaGetSymbolAddress(&pHF, g_HF);
    cudaGetSymbolAddress(&pXc, g_Xc);   cudaGetSymbolAddress(&pZc2, g_Zc2);
    cudaGetSymbolAddress(&pZc3, g_Zc3); cudaGetSymbolAddress(&pHC, g_HC);
    cudaGetSymbolAddress(&pSxg, g_Sxg); cudaGetSymbolAddress(&pZs2, g_Zs2);
    cudaGetSymbolAddress(&pZs3, g_Zs3); cudaGetSymbolAddress(&pHS, g_HS);
    cudaGetSymbolAddress(&psup0, g_sup0); cudaGetSymbolAddress(&psup1, g_sup1);
    cudaGetSymbolAddress(&pacsT, g_acsT); cudaGetSymbolAddress(&pafcT, g_afcT);

    // 1. layout transposes
    transpose_in<<<(N_ * C_ * V_ * L_ + 255) / 256, 256>>>(x);
    transpose_acs<<<(S_ * VC_ + 255) / 256, 256>>>(acs);
    transpose_afc<<<(VC_ * V_ + 255) / 256, 256>>>(afc);

    // 2. fine level: HF = b + W1*x; Z2 = W2*x; Z3 = W3*x; HF += A0^T Z2 + A1^T Z3
    chanmix<<<V_, 192>>>((const float*)pX, W, b, (float*)pHF, (float*)pZ2, (float*)pZ3);
    launch_gemm(support,                pZ2, pHF, V_, V_, 1, 1.f);
    launch_gemm(support + (size_t)V_ * V_, pZ3, pHF, V_, V_, 1, 1.f);

    // 3. coarse level: Xc = afc^T X; HC = b + W1*Xc + B0^T(W2*Xc) + B1^T(W3*Xc)
    launch_gemm(afc, pX, pXc, VC_, V_, 0, 1.f);
    chanmix<<<VC_, 192>>>((const float*)pXc, W, b, (float*)pHC, (float*)pZc2, (float*)pZc3);
    launch_gemm(support_c,                   pZc2, pHC, VC_, VC_, 1, 1.f);
    launch_gemm(support_c + (size_t)VC_ * VC_, pZc3, pHC, VC_, VC_, 1, 1.f);

    // 4. super level input: Sxg = acs^T Xc
    launch_gemm(acs, pXc, pSxg, S_, VC_, 0, 1.f);

    // 5. data-dependent super supports
    asmat_kernel<<<S_, 256>>>();
    supmat_kernel<<<1, 64>>>();

    // 6. super gcn: HS = b + W1*Sxg + S0^T(W2*Sxg) + S1^T(W3*Sxg)
    chanmix<<<S_, 192>>>((const float*)pSxg, W, b, (float*)pHS, (float*)pZs2, (float*)pZs3);
    launch_gemm(psup0, pZs2, pHS, S_, S_, 1, 1.f);
    launch_gemm(psup1, pZs3, pHS, S_, S_, 1, 1.f);

    // 7. hierarchical residual fusions (order matters)
    launch_gemm(pacsT, pHS, pHC, VC_, S_,  2, N1F);  // hc += N1*relu(acs @ hs)
    launch_gemm(pafcT, pHC, pHF, V_,  VC_, 2, N2F);  // hf += N2*relu(afc @ hc)
    launch_gemm(afc,   pHF, pHC, VC_, V_,  2, N3F);  // hc += N3*relu(afc^T @ hf)
    launch_gemm(acs,   pHC, pHS, S_,  VC_, 2, N4F);  // hs += N4*relu(acs^T @ hc)

    // 8. write out (hf, hc, hs)
    transpose_out<<<(N_ * CO_ * (V_ + VC_ + S_) * L_ + 255) / 256, 256>>>(out);
}

// round 2
// speedup vs baseline: 2.2875x; 2.2875x over previous
#include <cuda_runtime.h>
#include <math.h>

// dims
#define N_  16
#define C_  32
#define V_  2048
#define VC_ 256
#define S_  64
#define L_  12
#define CO_ 32
#define NL_ 192        // N_*L_
#define M_  6144       // C_*N_*L_  (column index m = c*192 + n*12 + l)

// residual fusion scales
#define N1F 0.8f
#define N2F 0.2f
#define N3F 0.2f
#define N4F 0.2f

// ---------------- scratch (static device arrays; no allocs allowed) ----------------
__device__ float g_X  [V_  * M_];
__device__ float g_Z2 [V_  * M_];
__device__ float g_Z3 [V_  * M_];
__device__ float g_HF [V_  * M_];
__device__ float g_Xc [VC_ * M_];
__device__ float g_Zc2[VC_ * M_];
__device__ float g_Zc3[VC_ * M_];
__device__ float g_HC [VC_ * M_];
__device__ float g_Sxg[S_  * M_];
__device__ float g_Zs2[S_  * M_];
__device__ float g_Zs3[S_  * M_];
__device__ float g_HS [S_  * M_];
__device__ float g_asmat[S_ * S_];
__device__ float g_sup0 [S_ * S_];
__device__ float g_sup1 [S_ * S_];
__device__ float g_acsT [S_ * VC_];   // acsT[s][w] = acs[w][s]
__device__ float g_afcT [VC_ * V_];   // afcT[w][v] = afc[v][w]

__device__ __forceinline__ unsigned f2tf32(float f) {
    unsigned u;
    asm("cvt.rna.tf32.f32 %0, %1;" : "=r"(u) : "f"(f));
    return u;
}

// ---------------- transpose x [N,C,V,L] -> X [V, M] ----------------
__global__ void transpose_in(const float* __restrict__ x) {
    int idx = blockIdx.x * blockDim.x + threadIdx.x;
    if (idx >= N_ * C_ * V_ * L_) return;
    int l = idx % L_;
    int v = (idx / L_) % V_;
    int c = (idx / (L_ * V_)) % C_;
    int n = idx / (L_ * V_ * C_);
    g_X[(size_t)v * M_ + c * NL_ + n * L_ + l] = x[idx];
}

__global__ void transpose_acs(const float* __restrict__ acs) {
    int idx = blockIdx.x * blockDim.x + threadIdx.x;
    if (idx >= S_ * VC_) return;
    int s = idx / VC_, w = idx % VC_;
    g_acsT[idx] = acs[w * S_ + s];
}

__global__ void transpose_afc(const float* __restrict__ afc) {
    int idx = blockIdx.x * blockDim.x + threadIdx.x;
    if (idx >= VC_ * V_) return;
    int w = idx / V_, v = idx % V_;
    g_afcT[idx] = afc[(size_t)v * VC_ + w];
}

// ---------------- channel mix: H = b + W1*Xin, Z2 = W2*Xin, Z3 = W3*Xin ----------------
__global__ void chanmix(const float* __restrict__ Xin,
                        const float* __restrict__ W,   // [32, 96]
                        const float* __restrict__ b,   // [32]
                        float* __restrict__ H,
                        float* __restrict__ Z2,
                        float* __restrict__ Z3) {
    __shared__ float sX[M_];      // 24 KB
    __shared__ float sW[32 * 96]; // 12 KB
    __shared__ float sb[32];
    int r = blockIdx.x;
    const float* xr = Xin + (size_t)r * M_;
    for (int i = threadIdx.x; i < M_; i += 192)      sX[i] = xr[i];
    for (int i = threadIdx.x; i < 32 * 96; i += 192) sW[i] = W[i];
    if (threadIdx.x < 32) sb[threadIdx.x] = b[threadIdx.x];
    __syncthreads();

    int nl = threadIdx.x;  // 0..191
    float xv[32];
    #pragma unroll
    for (int c = 0; c < 32; c++) xv[c] = sX[c * NL_ + nl];

    for (int o = 0; o < 32; o++) {
        const float* wr = &sW[o * 96];
        float a0 = sb[o], a1 = 0.f, a2 = 0.f;
        #pragma unroll
        for (int c = 0; c < 32; c++) {
            float xc = xv[c];
            a0 = fmaf(wr[c],      xc, a0);
            a1 = fmaf(wr[32 + c], xc, a1);
            a2 = fmaf(wr[64 + c], xc, a2);
        }
        size_t base = (size_t)r * M_ + o * NL_ + nl;
        H[base]  = a0;
        Z2[base] = a1;
        Z3[base] = a2;
    }
}

// ---------------- TN GEMM (tf32 tensor cores): C[mo,mn] (op) sum_k A[k,mo]*B[k,mn] -----
// A: [K x Mo] k-major, B: [K x Mn] k-major, C: [Mo x Mn] row-major.
// mode 0: C = acc;  mode 1: C += acc;  mode 2: C += alpha * relu(acc)
// Block tile 128x128, 8 warps of 64x32, K-chunk 16, mma.m16n8k8.tf32.
#define SMS 136   // smem row stride (floats): bank = (8k+m)%32 -> conflict-free frags
__global__ void __launch_bounds__(256, 2)
gemm_tf32(const float* __restrict__ A, const float* __restrict__ B, float* __restrict__ C,
          int Mo, int Mn, int K, int mode, float alpha) {
    __shared__ unsigned As[16][SMS];
    __shared__ unsigned Bs[16][SMS];

    const int bm = blockIdx.y * 128;
    const int bn = blockIdx.x * 128;
    const int tid  = threadIdx.x;
    const int lane = tid & 31;
    const int gid  = lane >> 2;   // 0..7
    const int qc   = lane & 3;    // 0..3
    const int warp = tid >> 5;
    const int wm   = warp >> 2;   // 0..1
    const int wn   = warp & 3;    // 0..3
    const int m_base = wm * 64;
    const int n_base = wn * 32;

    // loader indices: two k-rows per thread (lk, lk+8), 4 consecutive cols
    const int lk = tid >> 5;          // 0..7
    const int lm = (tid & 31) << 2;   // 0..124

    float acc[4][4][4];
    #pragma unroll
    for (int i = 0; i < 4; i++)
        #pragma unroll
        for (int j = 0; j < 4; j++)
            #pragma unroll
            for (int t = 0; t < 4; t++) acc[i][j][t] = 0.f;

    // prologue: fetch chunk 0
    float4 va[2], vb[2];
    {
        const int mc = bm + lm;
        #pragma unroll
        for (int kk = 0; kk < 2; kk++) {
            int kr = lk + kk * 8;
            va[kk] = make_float4(0.f, 0.f, 0.f, 0.f);
            if (mc < Mo) va[kk] = *reinterpret_cast<const float4*>(A + (size_t)kr * Mo + mc);
            vb[kk] = *reinterpret_cast<const float4*>(B + (size_t)kr * Mn + bn + lm);
        }
    }

    for (int k0 = 0; k0 < K; k0 += 16) {
        // store current chunk (converted to tf32) into smem
        #pragma unroll
        for (int kk = 0; kk < 2; kk++) {
            uint4 ua = make_uint4(f2tf32(va[kk].x), f2tf32(va[kk].y),
                                  f2tf32(va[kk].z), f2tf32(va[kk].w));
            uint4 ub = make_uint4(f2tf32(vb[kk].x), f2tf32(vb[kk].y),
                                  f2tf32(vb[kk].z), f2tf32(vb[kk].w));
            *reinterpret_cast<uint4*>(&As[lk + kk * 8][lm]) = ua;
            *reinterpret_cast<uint4*>(&Bs[lk + kk * 8][lm]) = ub;
        }
        __syncthreads();

        // prefetch next chunk into registers
        if (k0 + 16 < K) {
            const int mc = bm + lm;
            #pragma unroll
            for (int kk = 0; kk < 2; kk++) {
                int kr = k0 + 16 + lk + kk * 8;
                va[kk] = make_float4(0.f, 0.f, 0.f, 0.f);
                if (mc < Mo) va[kk] = *reinterpret_cast<const float4*>(A + (size_t)kr * Mo + mc);
                vb[kk] = *reinterpret_cast<const float4*>(B + (size_t)kr * Mn + bn + lm);
            }
        }

        // compute: two k8 steps
        #pragma unroll
        for (int ks = 0; ks < 2; ks++) {
            const int kk = ks * 8;
            unsigned af[4][4];
            #pragma unroll
            for (int i = 0; i < 4; i++) {
                int mb = m_base + i * 16;
                af[i][0] = As[kk + qc    ][mb + gid    ];
                af[i][1] = As[kk + qc    ][mb + gid + 8];
                af[i][2] = As[kk + qc + 4][mb + gid    ];
                af[i][3] = As[kk + qc + 4][mb + gid + 8];
            }
            unsigned bf[4][2];
            #pragma unroll
            for (int j = 0; j < 4; j++) {
                int nb = n_base + j * 8;
                bf[j][0] = Bs[kk + qc    ][nb + gid];
                bf[j][1] = Bs[kk + qc + 4][nb + gid];
            }
            #pragma unroll
            for (int i = 0; i < 4; i++)
                #pragma unroll
                for (int j = 0; j < 4; j++) {
                    asm volatile(
                        "mma.sync.aligned.m16n8k8.row.col.f32.tf32.tf32.f32 "
                        "{%0,%1,%2,%3},{%4,%5,%6,%7},{%8,%9},{%0,%1,%2,%3};\n"
                        : "+f"(acc[i][j][0]), "+f"(acc[i][j][1]),
                          "+f"(acc[i][j][2]), "+f"(acc[i][j][3])
                        : "r"(af[i][0]), "r"(af[i][1]), "r"(af[i][2]), "r"(af[i][3]),
                          "r"(bf[j][0]), "r"(bf[j][1]));
                }
        }
        __syncthreads();
    }

    // epilogue
    #pragma unroll
    for (int i = 0; i < 4; i++) {
        int r0 = bm + m_base + i * 16 + gid;
        int r1 = r0 + 8;
        #pragma unroll
        for (int j = 0; j < 4; j++) {
            int col = bn + n_base + j * 8 + qc * 2;
            #pragma unroll
            for (int h = 0; h < 2; h++) {
                int row = h ? r1 : r0;
                if (row >= Mo) continue;
                float x0 = acc[i][j][h * 2 + 0];
                float x1 = acc[i][j][h * 2 + 1];
                float* cp = C + (size_t)row * Mn + col;
                float2 r;
                if (mode == 0) {
                    r = make_float2(x0, x1);
                } else {
                    float2 p = *reinterpret_cast<const float2*>(cp);
                    if (mode == 1) {
                        r = make_float2(p.x + x0, p.y + x1);
                    } else {
                        r = make_float2(p.x + alpha * fmaxf(x0, 0.f),
                                        p.y + alpha * fmaxf(x1, 0.f));
                    }
                }
                *reinterpret_cast<float2*>(cp) = r;
            }
        }
    }
}

// ---------------- as_mat[s,t] = relu(sum_j Sxg[s,j]*Sxg[t,perm(j)] - 0.5) ----------------
__global__ void asmat_kernel() {
    __shared__ float Ps[M_];  // 24 KB
    int s = blockIdx.x;
    for (int i = threadIdx.x; i < M_; i += blockDim.x)
        Ps[i] = g_Sxg[(size_t)s * M_ + i];
    __syncthreads();
    int warp = threadIdx.x >> 5, lane = threadIdx.x & 31;
    for (int t = warp; t < S_; t += 8) {
        float acc = 0.f;
        const float* qt = &g_Sxg[(size_t)t * M_];
        for (int j = lane; j < M_; j += 32) {
            int cp = j & 31;
            int np = (j >> 5) & 15;
            int lp = j >> 9;
            int pj = cp * NL_ + np * L_ + lp;
            acc = fmaf(Ps[j], qt[pj], acc);
        }
        #pragma unroll
        for (int o = 16; o > 0; o >>= 1) acc += __shfl_down_sync(0xffffffffu, acc, o);
        if (lane == 0) {
            float v = acc - 0.5f;
            g_asmat[s * S_ + t] = v > 0.f ? v : 0.f;
        }
    }
}

// ---------------- sup0 = softmax(rownorm(as_mat)), sup1 = softmax(rownorm(as_mat^T)) -----
__global__ void supmat_kernel() {
    __shared__ float Ms[S_ * S_];
    int t = threadIdx.x;
    for (int i = t; i < S_ * S_; i += blockDim.x) Ms[i] = g_asmat[i];
    __syncthreads();
    if (t >= S_) return;
    float vals[S_];
    {
        float rs = 0.f;
        for (int u = 0; u < S_; u++) rs += Ms[t * S_ + u];
        float dinv = rs > 0.f ? 1.f / rs : 0.f;
        float mx = -1e30f;
        for (int u = 0; u < S_; u++) { vals[u] = Ms[t * S_ + u] * dinv; mx = fmaxf(mx, vals[u]); }
        float se = 0.f;
        for (int u = 0; u < S_; u++) { vals[u] = expf(vals[u] - mx); se += vals[u]; }
        float inv = 1.f / se;
        for (int u = 0; u < S_; u++) g_sup0[t * S_ + u] = vals[u] * inv;
    }
    {
        float cs = 0.f;
        for (int u = 0; u < S_; u++) cs += Ms[u * S_ + t];
        float dinv = cs > 0.f ? 1.f / cs : 0.f;
        float mx = -1e30f;
        for (int u = 0; u < S_; u++) { vals[u] = Ms[u * S_ + t] * dinv; mx = fmaxf(mx, vals[u]); }
        float se = 0.f;
        for (int u = 0; u < S_; u++) { vals[u] = expf(vals[u] - mx); se += vals[u]; }
        float inv = 1.f / se;
        for (int u = 0; u < S_; u++) g_sup1[t * S_ + u] = vals[u] * inv;
    }
}

// ---------------- write outputs: hf [N,CO,V,L], hc [N,CO,VC,L], hs [N,CO,S,L] ----------------
__global__ void transpose_out(float* __restrict__ out) {
    const int HFsz = N_ * CO_ * V_ * L_;
    const int HCsz = N_ * CO_ * VC_ * L_;
    const int HSsz = N_ * CO_ * S_ * L_;
    int idx = blockIdx.x * blockDim.x + threadIdx.x;
    if (idx < HFsz) {
        int l = idx % L_;
        int v = (idx / L_) % V_;
        int o = (idx / (L_ * V_)) % CO_;
        int n = idx / (L_ * V_ * CO_);
        out[idx] = g_HF[(size_t)v * M_ + o * NL_ + n * L_ + l];
    } else if (idx < HFsz + HCsz) {
        int k = idx - HFsz;
        int l = k % L_;
        int w = (k / L_) % VC_;
        int o = (k / (L_ * VC_)) % CO_;
        int n = k / (L_ * VC_ * CO_);
        out[idx] = g_HC[(size_t)w * M_ + o * NL_ + n * L_ + l];
    } else if (idx < HFsz + HCsz + HSsz) {
        int k = idx - HFsz - HCsz;
        int l = k % L_;
        int s = (k / L_) % S_;
        int o = (k / (L_ * S_)) % CO_;
        int n = k / (L_ * S_ * CO_);
        out[idx] = g_HS[(size_t)s * M_ + o * NL_ + n * L_ + l];
    }
}

// ---------------- host side ----------------
static inline void launch_gemm(const void* A, const void* B, void* C,
                               int Mo, int K, int mode, float alpha) {
    dim3 grid(M_ / 128, (Mo + 127) / 128);
    gemm_tf32<<<grid, 256>>>((const float*)A, (const float*)B, (float*)C,
                             Mo, M_, K, mode, alpha);
}

extern "C" void kernel_launch(void* const* d_in, const int* in_sizes, int n_in,
                              void* d_out, int out_size) {
    (void)in_sizes; (void)n_in; (void)out_size;
    const float* x         = (const float*)d_in[0];
    const float* support   = (const float*)d_in[1];  // [2, V, V]
    const float* support_c = (const float*)d_in[2];  // [2, VC, VC]
    const float* acs       = (const float*)d_in[3];  // [VC, S]
    const float* afc       = (const float*)d_in[4];  // [V, VC]
    const float* W         = (const float*)d_in[5];  // [CO, 3C]
    const float* b         = (const float*)d_in[6];  // [CO]
    float* out = (float*)d_out;

    void *pX, *pZ2, *pZ3, *pHF, *pXc, *pZc2, *pZc3, *pHC;
    void *pSxg, *pZs2, *pZs3, *pHS, *psup0, *psup1, *pacsT, *pafcT;
    cudaGetSymbolAddress(&pX, g_X);     cudaGetSymbolAddress(&pZ2, g_Z2);
    cudaGetSymbolAddress(&pZ3, g_Z3);   cudaGetSymbolAddress(&pHF, g_HF);
    cudaGetSymbolAddress(&pXc, g_Xc);   cudaGetSymbolAddress(&pZc2, g_Zc2);
    cudaGetSymbolAddress(&pZc3, g_Zc3); cudaGetSymbolAddress(&pHC, g_HC);
    cudaGetSymbolAddress(&pSxg, g_Sxg); cudaGetSymbolAddress(&pZs2, g_Zs2);
    cudaGetSymbolAddress(&pZs3, g_Zs3); cudaGetSymbolAddress(&pHS, g_HS);
    cudaGetSymbolAddress(&psup0, g_sup0); cudaGetSymbolAddress(&psup1, g_sup1);
    cudaGetSymbolAddress(&pacsT, g_acsT); cudaGetSymbolAddress(&pafcT, g_afcT);

    // 1. layout transposes
    transpose_in<<<(N_ * C_ * V_ * L_ + 255) / 256, 256>>>(x);
    transpose_acs<<<(S_ * VC_ + 255) / 256, 256>>>(acs);
    transpose_afc<<<(VC_ * V_ + 255) / 256, 256>>>(afc);

    // 2. fine level: HF = b + W1*x; Z2 = W2*x; Z3 = W3*x; HF += A0^T Z2 + A1^T Z3
    chanmix<<<V_, 192>>>((const float*)pX, W, b, (float*)pHF, (float*)pZ2, (float*)pZ3);
    launch_gemm(support,                   pZ2, pHF, V_, V_, 1, 1.f);
    launch_gemm(support + (size_t)V_ * V_, pZ3, pHF, V_, V_, 1, 1.f);

    // 3. coarse level
    launch_gemm(afc, pX, pXc, VC_, V_, 0, 1.f);
    chanmix<<<VC_, 192>>>((const float*)pXc, W, b, (float*)pHC, (float*)pZc2, (float*)pZc3);
    launch_gemm(support_c,                     pZc2, pHC, VC_, VC_, 1, 1.f);
    launch_gemm(support_c + (size_t)VC_ * VC_, pZc3, pHC, VC_, VC_, 1, 1.f);

    // 4. super level input: Sxg = acs^T Xc
    launch_gemm(acs, pXc, pSxg, S_, VC_, 0, 1.f);

    // 5. data-dependent super supports (exact fp32)
    asmat_kernel<<<S_, 256>>>();
    supmat_kernel<<<1, 64>>>();

    // 6. super gcn
    chanmix<<<S_, 192>>>((const float*)pSxg, W, b, (float*)pHS, (float*)pZs2, (float*)pZs3);
    launch_gemm(psup0, pZs2, pHS, S_, S_, 1, 1.f);
    launch_gemm(psup1, pZs3, pHS, S_, S_, 1, 1.f);

    // 7. hierarchical residual fusions (order matters)
    launch_gemm(pacsT, pHS, pHC, VC_, S_,  2, N1F);
    launch_gemm(pafcT, pHC, pHF, V_,  VC_, 2, N2F);
    launch_gemm(afc,   pHF, pHC, VC_, V_,  2, N3F);
    launch_gemm(acs,   pHC, pHS, S_,  VC_, 2, N4F);

    // 8. write out
    transpose_out<<<(N_ * CO_ * (V_ + VC_ + S_) * L_ + 255) / 256, 256>>>(out);
}

// round 3
// speedup vs baseline: 2.3017x; 1.0062x over previous
#include <cuda_runtime.h>
#include <math.h>

// dims
#define N_  16
#define C_  32
#define V_  2048
#define VC_ 256
#define S_  64
#define L_  12
#define CO_ 32
#define NL_ 192        // N_*L_
#define M_  6144       // C_*N_*L_  (column index m = c*192 + n*12 + l)

// residual fusion scales
#define N1F 0.8f
#define N2F 0.2f
#define N3F 0.2f
#define N4F 0.2f

// ---------------- scratch (static device arrays; no allocs allowed) ----------------
__device__ float g_X  [V_  * M_];
__device__ float g_Z2 [V_  * M_];
__device__ float g_Z3 [V_  * M_];
__device__ float g_HF [V_  * M_];
__device__ float g_Xc [VC_ * M_];
__device__ float g_Zc2[VC_ * M_];
__device__ float g_Zc3[VC_ * M_];
__device__ float g_HC [VC_ * M_];
__device__ float g_Sxg[S_  * M_];
__device__ float g_Zs2[S_  * M_];
__device__ float g_Zs3[S_  * M_];
__device__ float g_HS [S_  * M_];
__device__ float g_asmat[S_ * S_];
__device__ float g_sup0 [S_ * S_];
__device__ float g_sup1 [S_ * S_];
__device__ float g_acsT [S_ * VC_];   // acsT[s][w] = acs[w][s]
__device__ float g_afcT [VC_ * V_];   // afcT[w][v] = afc[v][w]

__device__ __forceinline__ unsigned f2tf32(float f) {
    unsigned u;
    asm("cvt.rna.tf32.f32 %0, %1;" : "=r"(u) : "f"(f));
    return u;
}

// ---------------- transpose x [N,C,V,L] -> X [V, M] ----------------
__global__ void transpose_in(const float* __restrict__ x) {
    int idx = blockIdx.x * blockDim.x + threadIdx.x;
    if (idx >= N_ * C_ * V_ * L_) return;
    int l = idx % L_;
    int v = (idx / L_) % V_;
    int c = (idx / (L_ * V_)) % C_;
    int n = idx / (L_ * V_ * C_);
    g_X[(size_t)v * M_ + c * NL_ + n * L_ + l] = x[idx];
}

__global__ void transpose_acs(const float* __restrict__ acs) {
    int idx = blockIdx.x * blockDim.x + threadIdx.x;
    if (idx >= S_ * VC_) return;
    int s = idx / VC_, w = idx % VC_;
    g_acsT[idx] = acs[w * S_ + s];
}

__global__ void transpose_afc(const float* __restrict__ afc) {
    int idx = blockIdx.x * blockDim.x + threadIdx.x;
    if (idx >= VC_ * V_) return;
    int w = idx / V_, v = idx % V_;
    g_afcT[idx] = afc[(size_t)v * VC_ + w];
}

// ---------------- channel mix: H = b + W1*Xin, Z2 = W2*Xin, Z3 = W3*Xin ----------------
__global__ void chanmix(const float* __restrict__ Xin,
                        const float* __restrict__ W,   // [32, 96]
                        const float* __restrict__ b,   // [32]
                        float* __restrict__ H,
                        float* __restrict__ Z2,
                        float* __restrict__ Z3) {
    __shared__ float sX[M_];      // 24 KB
    __shared__ float sW[32 * 96]; // 12 KB
    __shared__ float sb[32];
    int r = blockIdx.x;
    const float* xr = Xin + (size_t)r * M_;
    for (int i = threadIdx.x; i < M_; i += 192)      sX[i] = xr[i];
    for (int i = threadIdx.x; i < 32 * 96; i += 192) sW[i] = W[i];
    if (threadIdx.x < 32) sb[threadIdx.x] = b[threadIdx.x];
    __syncthreads();

    int nl = threadIdx.x;  // 0..191
    float xv[32];
    #pragma unroll
    for (int c = 0; c < 32; c++) xv[c] = sX[c * NL_ + nl];

    for (int o = 0; o < 32; o++) {
        const float* wr = &sW[o * 96];
        float a0 = sb[o], a1 = 0.f, a2 = 0.f;
        #pragma unroll
        for (int c = 0; c < 32; c++) {
            float xc = xv[c];
            a0 = fmaf(wr[c],      xc, a0);
            a1 = fmaf(wr[32 + c], xc, a1);
            a2 = fmaf(wr[64 + c], xc, a2);
        }
        size_t base = (size_t)r * M_ + o * NL_ + nl;
        H[base]  = a0;
        Z2[base] = a1;
        Z3[base] = a2;
    }
}

// ---------------- TN GEMM (tf32 tensor cores): C[mo,mn] (op) sum_k A[k,mo]*B[k,mn] -----
// A: [K x Mo] k-major, B: [K x Mn] k-major, C: [Mo x Mn] row-major.
// mode 0: C = acc;  mode 1: C += acc;  mode 2: C += alpha * relu(acc)
// Block tile 128x128, 8 warps of 64x32, K-chunk 16, mma.m16n8k8.tf32.
#define SMS 136   // smem row stride (floats): bank = (8k+m)%32 -> conflict-free frags
__global__ void __launch_bounds__(256, 2)
gemm_tf32(const float* __restrict__ A, const float* __restrict__ B, float* __restrict__ C,
          int Mo, int Mn, int K, int mode, float alpha) {
    __shared__ unsigned As[16][SMS];
    __shared__ unsigned Bs[16][SMS];

    const int bm = blockIdx.y * 128;
    const int bn = blockIdx.x * 128;
    const int tid  = threadIdx.x;
    const int lane = tid & 31;
    const int gid  = lane >> 2;   // 0..7
    const int qc   = lane & 3;    // 0..3
    const int warp = tid >> 5;
    const int wm   = warp >> 2;   // 0..1
    const int wn   = warp & 3;    // 0..3
    const int m_base = wm * 64;
    const int n_base = wn * 32;

    // loader indices: two k-rows per thread (lk, lk+8), 4 consecutive cols
    const int lk = tid >> 5;          // 0..7
    const int lm = (tid & 31) << 2;   // 0..124

    float acc[4][4][4];
    #pragma unroll
    for (int i = 0; i < 4; i++)
        #pragma unroll
        for (int j = 0; j < 4; j++)
            #pragma unroll
            for (int t = 0; t < 4; t++) acc[i][j][t] = 0.f;

    // prologue: fetch chunk 0
    float4 va[2], vb[2];
    {
        const int mc = bm + lm;
        #pragma unroll
        for (int kk = 0; kk < 2; kk++) {
            int kr = lk + kk * 8;
            va[kk] = make_float4(0.f, 0.f, 0.f, 0.f);
            if (mc < Mo) va[kk] = *reinterpret_cast<const float4*>(A + (size_t)kr * Mo + mc);
            vb[kk] = *reinterpret_cast<const float4*>(B + (size_t)kr * Mn + bn + lm);
        }
    }

    for (int k0 = 0; k0 < K; k0 += 16) {
        // store current chunk (converted to tf32) into smem
        #pragma unroll
        for (int kk = 0; kk < 2; kk++) {
            uint4 ua = make_uint4(f2tf32(va[kk].x), f2tf32(va[kk].y),
                                  f2tf32(va[kk].z), f2tf32(va[kk].w));
            uint4 ub = make_uint4(f2tf32(vb[kk].x), f2tf32(vb[kk].y),
                                  f2tf32(vb[kk].z), f2tf32(vb[kk].w));
            *reinterpret_cast<uint4*>(&As[lk + kk * 8][lm]) = ua;
            *reinterpret_cast<uint4*>(&Bs[lk + kk * 8][lm]) = ub;
        }
        __syncthreads();

        // prefetch next chunk into registers
        if (k0 + 16 < K) {
            const int mc = bm + lm;
            #pragma unroll
            for (int kk = 0; kk < 2; kk++) {
                int kr = k0 + 16 + lk + kk * 8;
                va[kk] = make_float4(0.f, 0.f, 0.f, 0.f);
                if (mc < Mo) va[kk] = *reinterpret_cast<const float4*>(A + (size_t)kr * Mo + mc);
                vb[kk] = *reinterpret_cast<const float4*>(B + (size_t)kr * Mn + bn + lm);
            }
        }

        // compute: two k8 steps
        #pragma unroll
        for (int ks = 0; ks < 2; ks++) {
            const int kk = ks * 8;
            unsigned af[4][4];
            #pragma unroll
            for (int i = 0; i < 4; i++) {
                int mb = m_base + i * 16;
                af[i][0] = As[kk + qc    ][mb + gid    ];
                af[i][1] = As[kk + qc    ][mb + gid + 8];
                af[i][2] = As[kk + qc + 4][mb + gid    ];
                af[i][3] = As[kk + qc + 4][mb + gid + 8];
            }
            unsigned bf[4][2];
            #pragma unroll
            for (int j = 0; j < 4; j++) {
                int nb = n_base + j * 8;
                bf[j][0] = Bs[kk + qc    ][nb + gid];
                bf[j][1] = Bs[kk + qc + 4][nb + gid];
            }
            #pragma unroll
            for (int i = 0; i < 4; i++)
                #pragma unroll
                for (int j = 0; j < 4; j++) {
                    asm volatile(
                        "mma.sync.aligned.m16n8k8.row.col.f32.tf32.tf32.f32 "
                        "{%0,%1,%2,%3},{%4,%5,%6,%7},{%8,%9},{%0,%1,%2,%3};\n"
                        : "+f"(acc[i][j][0]), "+f"(acc[i][j][1]),
                          "+f"(acc[i][j][2]), "+f"(acc[i][j][3])
                        : "r"(af[i][0]), "r"(af[i][1]), "r"(af[i][2]), "r"(af[i][3]),
                          "r"(bf[j][0]), "r"(bf[j][1]));
                }
        }
        __syncthreads();
    }

    // epilogue
    #pragma unroll
    for (int i = 0; i < 4; i++) {
        int r0 = bm + m_base + i * 16 + gid;
        int r1 = r0 + 8;
        #pragma unroll
        for (int j = 0; j < 4; j++) {
            int col = bn + n_base + j * 8 + qc * 2;
            #pragma unroll
            for (int h = 0; h < 2; h++) {
                int row = h ? r1 : r0;
                if (row >= Mo) continue;
                float x0 = acc[i][j][h * 2 + 0];
                float x1 = acc[i][j][h * 2 + 1];
                float* cp = C + (size_t)row * Mn + col;
                float2 r;
                if (mode == 0) {
                    r = make_float2(x0, x1);
                } else {
                    float2 p = *reinterpret_cast<const float2*>(cp);
                    if (mode == 1) {
                        r = make_float2(p.x + x0, p.y + x1);
                    } else {
                        r = make_float2(p.x + alpha * fmaxf(x0, 0.f),
                                        p.y + alpha * fmaxf(x1, 0.f));
                    }
                }
                *reinterpret_cast<float2*>(cp) = r;
            }
        }
    }
}

// ---------------- as_mat[s,t] = relu(sum_j Sxg[s,j]*Sxg[t,perm(j)] - 0.5) ----------------
__global__ void asmat_kernel() {
    __shared__ float Ps[M_];  // 24 KB
    int s = blockIdx.x;
    for (int i = threadIdx.x; i < M_; i += blockDim.x)
        Ps[i] = g_Sxg[(size_t)s * M_ + i];
    __syncthreads();
    int warp = threadIdx.x >> 5, lane = threadIdx.x & 31;
    for (int t = warp; t < S_; t += 8) {
        float acc = 0.f;
        const float* qt = &g_Sxg[(size_t)t * M_];
        for (int j = lane; j < M_; j += 32) {
            int cp = j & 31;
            int np = (j >> 5) & 15;
            int lp = j >> 9;
            int pj = cp * NL_ + np * L_ + lp;
            acc = fmaf(Ps[j], qt[pj], acc);
        }
        #pragma unroll
        for (int o = 16; o > 0; o >>= 1) acc += __shfl_down_sync(0xffffffffu, acc, o);
        if (lane == 0) {
            float v = acc - 0.5f;
            g_asmat[s * S_ + t] = v > 0.f ? v : 0.f;
        }
    }
}

// ---------------- sup0 = softmax(rownorm(as_mat)), sup1 = softmax(rownorm(as_mat^T)) -----
__global__ void supmat_kernel() {
    __shared__ float Ms[S_ * S_];
    int t = threadIdx.x;
    for (int i = t; i < S_ * S_; i += blockDim.x) Ms[i] = g_asmat[i];
    __syncthreads();
    if (t >= S_) return;
    float vals[S_];
    {
        float rs = 0.f;
        for (int u = 0; u < S_; u++) rs += Ms[t * S_ + u];
        float dinv = rs > 0.f ? 1.f / rs : 0.f;
        float mx = -1e30f;
        for (int u = 0; u < S_; u++) { vals[u] = Ms[t * S_ + u] * dinv; mx = fmaxf(mx, vals[u]); }
        float se = 0.f;
        for (int u = 0; u < S_; u++) { vals[u] = expf(vals[u] - mx); se += vals[u]; }
        float inv = 1.f / se;
        for (int u = 0; u < S_; u++) g_sup0[t * S_ + u] = vals[u] * inv;
    }
    {
        float cs = 0.f;
        for (int u = 0; u < S_; u++) cs += Ms[u * S_ + t];
        float dinv = cs > 0.f ? 1.f / cs : 0.f;
        float mx = -1e30f;
        for (int u = 0; u < S_; u++) { vals[u] = Ms[u * S_ + t] * dinv; mx = fmaxf(mx, vals[u]); }
        float se = 0.f;
        for (int u = 0; u < S_; u++) { vals[u] = expf(vals[u] - mx); se += vals[u]; }
        float inv = 1.f / se;
        for (int u = 0; u < S_; u++) g_sup1[t * S_ + u] = vals[u] * inv;
    }
}

// ---------------- write outputs: hf [N,CO,V,L], hc [N,CO,VC,L], hs [N,CO,S,L] ----------------
__global__ void transpose_out(float* __restrict__ out) {
    const int HFsz = N_ * CO_ * V_ * L_;
    const int HCsz = N_ * CO_ * VC_ * L_;
    const int HSsz = N_ * CO_ * S_ * L_;
    int idx = blockIdx.x * blockDim.x + threadIdx.x;
    if (idx < HFsz) {
        int l = idx % L_;
        int v = (idx / L_) % V_;
        int o = (idx / (L_ * V_)) % CO_;
        int n = idx / (L_ * V_ * CO_);
        out[idx] = g_HF[(size_t)v * M_ + o * NL_ + n * L_ + l];
    } else if (idx < HFsz + HCsz) {
        int k = idx - HFsz;
        int l = k % L_;
        int w = (k / L_) % VC_;
        int o = (k / (L_ * VC_)) % CO_;
        int n = k / (L_ * VC_ * CO_);
        out[idx] = g_HC[(size_t)w * M_ + o * NL_ + n * L_ + l];
    } else if (idx < HFsz + HCsz + HSsz) {
        int k = idx - HFsz - HCsz;
        int l = k % L_;
        int s = (k / L_) % S_;
        int o = (k / (L_ * S_)) % CO_;
        int n = k / (L_ * S_ * CO_);
        out[idx] = g_HS[(size_t)s * M_ + o * NL_ + n * L_ + l];
    }
}

// ---------------- host side ----------------
static inline void launch_gemm(const void* A, const void* B, void* C,
                               int Mo, int K, int mode, float alpha) {
    dim3 grid(M_ / 128, (Mo + 127) / 128);
    gemm_tf32<<<grid, 256>>>((const float*)A, (const float*)B, (float*)C,
                             Mo, M_, K, mode, alpha);
}

extern "C" void kernel_launch(void* const* d_in, const int* in_sizes, int n_in,
                              void* d_out, int out_size) {
    (void)in_sizes; (void)n_in; (void)out_size;
    const float* x         = (const float*)d_in[0];
    const float* support   = (const float*)d_in[1];  // [2, V, V]
    const float* support_c = (const float*)d_in[2];  // [2, VC, VC]
    const float* acs       = (const float*)d_in[3];  // [VC, S]
    const float* afc       = (const float*)d_in[4];  // [V, VC]
    const float* W         = (const float*)d_in[5];  // [CO, 3C]
    const float* b         = (const float*)d_in[6];  // [CO]
    float* out = (float*)d_out;

    void *pX, *pZ2, *pZ3, *pHF, *pXc, *pZc2, *pZc3, *pHC;
    void *pSxg, *pZs2, *pZs3, *pHS, *psup0, *psup1, *pacsT, *pafcT;
    cudaGetSymbolAddress(&pX, g_X);     cudaGetSymbolAddress(&pZ2, g_Z2);
    cudaGetSymbolAddress(&pZ3, g_Z3);   cudaGetSymbolAddress(&pHF, g_HF);
    cudaGetSymbolAddress(&pXc, g_Xc);   cudaGetSymbolAddress(&pZc2, g_Zc2);
    cudaGetSymbolAddress(&pZc3, g_Zc3); cudaGetSymbolAddress(&pHC, g_HC);
    cudaGetSymbolAddress(&pSxg, g_Sxg); cudaGetSymbolAddress(&pZs2, g_Zs2);
    cudaGetSymbolAddress(&pZs3, g_Zs3); cudaGetSymbolAddress(&pHS, g_HS);
    cudaGetSymbolAddress(&psup0, g_sup0); cudaGetSymbolAddress(&psup1, g_sup1);
    cudaGetSymbolAddress(&pacsT, g_acsT); cudaGetSymbolAddress(&pafcT, g_afcT);

    // 1. layout transposes
    transpose_in<<<(N_ * C_ * V_ * L_ + 255) / 256, 256>>>(x);
    transpose_acs<<<(S_ * VC_ + 255) / 256, 256>>>(acs);
    transpose_afc<<<(VC_ * V_ + 255) / 256, 256>>>(afc);

    // 2. fine level: HF = b + W1*x; Z2 = W2*x; Z3 = W3*x; HF += A0^T Z2 + A1^T Z3
    chanmix<<<V_, 192>>>((const float*)pX, W, b, (float*)pHF, (float*)pZ2, (float*)pZ3);
    launch_gemm(support,                   pZ2, pHF, V_, V_, 1, 1.f);
    launch_gemm(support + (size_t)V_ * V_, pZ3, pHF, V_, V_, 1, 1.f);

    // 3. coarse level
    launch_gemm(afc, pX, pXc, VC_, V_, 0, 1.f);
    chanmix<<<VC_, 192>>>((const float*)pXc, W, b, (float*)pHC, (float*)pZc2, (float*)pZc3);
    launch_gemm(support_c,                     pZc2, pHC, VC_, VC_, 1, 1.f);
    launch_gemm(support_c + (size_t)VC_ * VC_, pZc3, pHC, VC_, VC_, 1, 1.f);

    // 4. super level input: Sxg = acs^T Xc
    launch_gemm(acs, pXc, pSxg, S_, VC_, 0, 1.f);

    // 5. data-dependent super supports (exact fp32)
    asmat_kernel<<<S_, 256>>>();
    supmat_kernel<<<1, 64>>>();

    // 6. super gcn
    chanmix<<<S_, 192>>>((const float*)pSxg, W, b, (float*)pHS, (float*)pZs2, (float*)pZs3);
    launch_gemm(psup0, pZs2, pHS, S_, S_, 1, 1.f);
    launch_gemm(psup1, pZs3, pHS, S_, S_, 1, 1.f);

    // 7. hierarchical residual fusions (order matters)
    launch_gemm(pacsT, pHS, pHC, VC_, S_,  2, N1F);
    launch_gemm(pafcT, pHC, pHF, V_,  VC_, 2, N2F);
    launch_gemm(afc,   pHF, pHC, VC_, V_,  2, N3F);
    launch_gemm(acs,   pHC, pHS, S_,  VC_, 2, N4F);

    // 8. write out
    transpose_out<<<(N_ * CO_ * (V_ + VC_ + S_) * L_ + 255) / 256, 256>>>(out);
}

// round 6
// speedup vs baseline: 2.3920x; 1.0393x over previous
#include <cuda_runtime.h>
#include <cstdint>
#include <math.h>

// dims
#define N_  16
#define C_  32
#define V_  2048
#define VC_ 256
#define S_  64
#define L_  12
#define CO_ 32
#define NL_ 192        // N_*L_
#define M_  6144       // C_*N_*L_  (column index m = c*192 + n*12 + l)

// residual fusion scales
#define N1F 0.8f
#define N2F 0.2f
#define N3F 0.2f
#define N4F 0.2f

// ---------------- scratch (static device arrays; no allocs allowed) ----------------
__device__ float g_X  [V_  * M_];
__device__ float g_Z2 [V_  * M_];
__device__ float g_Z3 [V_  * M_];
__device__ float g_HF [V_  * M_];
__device__ float g_Xc [VC_ * M_];
__device__ float g_Zc2[VC_ * M_];
__device__ float g_Zc3[VC_ * M_];
__device__ float g_HC [VC_ * M_];
__device__ float g_Sxg[S_  * M_];
__device__ float g_Zs2[S_  * M_];
__device__ float g_Zs3[S_  * M_];
__device__ float g_HS [S_  * M_];
__device__ float g_asmat[S_ * S_];
__device__ float g_sup0 [S_ * S_];
__device__ float g_sup1 [S_ * S_];
__device__ float g_acsT [S_ * VC_];
__device__ float g_afcT [VC_ * V_];

__device__ __forceinline__ unsigned f2tf32(float f) {
    unsigned u;
    asm("cvt.rna.tf32.f32 %0, %1;" : "=r"(u) : "f"(f));
    return u;
}
__device__ __forceinline__ uint32_t smem_u32(const void* p) {
    uint32_t a;
    asm("{ .reg .u64 t; cvta.to.shared.u64 t, %1; cvt.u32.u64 %0, t; }" : "=r"(a) : "l"(p));
    return a;
}
#define CP_COMMIT() asm volatile("cp.async.commit_group;" ::: "memory")
#define CP_WAIT(n)  asm volatile("cp.async.wait_group %0;" :: "n"(n) : "memory")

// ---------------- transpose x [N,C,V,L] -> X [V, M] ----------------
__global__ void transpose_in(const float* __restrict__ x) {
    int idx = blockIdx.x * blockDim.x + threadIdx.x;
    if (idx >= N_ * C_ * V_ * L_) return;
    int l = idx % L_;
    int v = (idx / L_) % V_;
    int c = (idx / (L_ * V_)) % C_;
    int n = idx / (L_ * V_ * C_);
    g_X[(size_t)v * M_ + c * NL_ + n * L_ + l] = x[idx];
}

__global__ void transpose_acs(const float* __restrict__ acs) {
    int idx = blockIdx.x * blockDim.x + threadIdx.x;
    if (idx >= S_ * VC_) return;
    int s = idx / VC_, w = idx % VC_;
    g_acsT[idx] = acs[w * S_ + s];
}

__global__ void transpose_afc(const float* __restrict__ afc) {
    int idx = blockIdx.x * blockDim.x + threadIdx.x;
    if (idx >= VC_ * V_) return;
    int w = idx / V_, v = idx % V_;
    g_afcT[idx] = afc[(size_t)v * VC_ + w];
}

// ---------------- channel mix ----------------
__global__ void chanmix(const float* __restrict__ Xin,
                        const float* __restrict__ W,
                        const float* __restrict__ b,
                        float* __restrict__ H,
                        float* __restrict__ Z2,
                        float* __restrict__ Z3) {
    __shared__ float sX[M_];
    __shared__ float sW[32 * 96];
    __shared__ float sb[32];
    int r = blockIdx.x;
    const float* xr = Xin + (size_t)r * M_;
    for (int i = threadIdx.x; i < M_; i += 192)      sX[i] = xr[i];
    for (int i = threadIdx.x; i < 32 * 96; i += 192) sW[i] = W[i];
    if (threadIdx.x < 32) sb[threadIdx.x] = b[threadIdx.x];
    __syncthreads();
    int nl = threadIdx.x;
    float xv[32];
    #pragma unroll
    for (int c = 0; c < 32; c++) xv[c] = sX[c * NL_ + nl];
    for (int o = 0; o < 32; o++) {
        const float* wr = &sW[o * 96];
        float a0 = sb[o], a1 = 0.f, a2 = 0.f;
        #pragma unroll
        for (int c = 0; c < 32; c++) {
            float xc = xv[c];
            a0 = fmaf(wr[c],      xc, a0);
            a1 = fmaf(wr[32 + c], xc, a1);
            a2 = fmaf(wr[64 + c], xc, a2);
        }
        size_t base = (size_t)r * M_ + o * NL_ + nl;
        H[base]  = a0;
        Z2[base] = a1;
        Z3[base] = a2;
    }
}

// ---------------- TN GEMM (tf32 mma.sync, 4-stage cp.async pipeline) ----------------
// A: [K x Mo] k-major, B: [K x Mn] k-major, C: [Mo x Mn] row-major.
// C[mo,mn] (op) sum_k A[k,mo]*B[k,mn];  mode 0: =, 1: +=, 2: += alpha*relu
// Block tile 128x128, 8 warps of 64x32, K-chunk 16.
#define BK 16
#define STG 4
#define SRD 136                       // smem row stride (floats): conflict-free frags
#define STAGE_F (BK * SRD)            // floats per stage per matrix
#define SMEMF (2 * STG * STAGE_F)     // total floats (69632 B)
__global__ void __launch_bounds__(256, 2)
gemm_tf32(const float* __restrict__ A, const float* __restrict__ B, float* __restrict__ C,
          int Mo, int Mn, int K, int mode, float alpha) {
    extern __shared__ float sm[];
    const uint32_t sbase = smem_u32(sm);

    const int bm = blockIdx.y * 128;
    const int bn = blockIdx.x * 128;
    const int tid  = threadIdx.x;
    const int lane = tid & 31;
    const int gid  = lane >> 2;   // 0..7
    const int qc   = lane & 3;    // 0..3
    const int warp = tid >> 5;
    const int m_base = (warp >> 2) * 64;
    const int n_base = (warp & 3) * 32;

    // loader: 2 float4 per matrix per stage per thread
    const int lrow0 = tid >> 5;            // rows 0..7
    const int lc4   = (tid & 31) << 2;     // cols 0,4,...,124

    float acc[4][4][4];
    #pragma unroll
    for (int i = 0; i < 4; i++)
        #pragma unroll
        for (int j = 0; j < 4; j++)
            #pragma unroll
            for (int t = 0; t < 4; t++) acc[i][j][t] = 0.f;

    const int nch = K / BK;

    // ---- stage loader ----
    auto load_stage = [&](int chunk, int slot) {
        const int k0 = chunk * BK;
        #pragma unroll
        for (int h = 0; h < 2; h++) {
            const int row = lrow0 + h * 8;
            // A (guard columns beyond Mo with zero-fill)
            uint32_t da = sbase + (uint32_t)(slot * STAGE_F + row * SRD + lc4) * 4u;
            const float* ga = A + (size_t)(k0 + row) * Mo + bm + lc4;
            int sz = (bm + lc4 < Mo) ? 16 : 0;
            if (!sz) ga = A;  // keep address valid
            asm volatile("cp.async.cg.shared.global [%0], [%1], 16, %2;"
                         :: "r"(da), "l"(ga), "r"(sz));
            // B (always full range: Mn = 6144)
            uint32_t db = sbase + (uint32_t)((STG + slot) * STAGE_F + row * SRD + lc4) * 4u;
            const float* gb = B + (size_t)(k0 + row) * Mn + bn + lc4;
            asm volatile("cp.async.cg.shared.global [%0], [%1], 16;"
                         :: "r"(db), "l"(gb));
        }
    };

    // prologue: preload STG-1 stages
    #pragma unroll
    for (int s = 0; s < STG - 1; s++) {
        if (s < nch) load_stage(s, s);
        CP_COMMIT();
    }

    for (int ch = 0; ch < nch; ch++) {
        CP_WAIT(STG - 2);
        __syncthreads();

        int nx = ch + STG - 1;
        if (nx < nch) load_stage(nx, nx & (STG - 1));
        CP_COMMIT();

        const float* As = sm + (ch & (STG - 1)) * STAGE_F;
        const float* Bs = sm + (STG + (ch & (STG - 1))) * STAGE_F;

        #pragma unroll
        for (int ks = 0; ks < 2; ks++) {
            const int kk = ks * 8;
            unsigned af[4][4];
            #pragma unroll
            for (int i = 0; i < 4; i++) {
                int mb = m_base + i * 16;
                af[i][0] = f2tf32(As[(kk + qc    ) * SRD + mb + gid    ]);
                af[i][1] = f2tf32(As[(kk + qc    ) * SRD + mb + gid + 8]);
                af[i][2] = f2tf32(As[(kk + qc + 4) * SRD + mb + gid    ]);
                af[i][3] = f2tf32(As[(kk + qc + 4) * SRD + mb + gid + 8]);
            }
            unsigned bf[4][2];
            #pragma unroll
            for (int j = 0; j < 4; j++) {
                int nb = n_base + j * 8;
                bf[j][0] = f2tf32(Bs[(kk + qc    ) * SRD + nb + gid]);
                bf[j][1] = f2tf32(Bs[(kk + qc + 4) * SRD + nb + gid]);
            }
            #pragma unroll
            for (int i = 0; i < 4; i++)
                #pragma unroll
                for (int j = 0; j < 4; j++) {
                    asm volatile(
                        "mma.sync.aligned.m16n8k8.row.col.f32.tf32.tf32.f32 "
                        "{%0,%1,%2,%3},{%4,%5,%6,%7},{%8,%9},{%0,%1,%2,%3};\n"
                        : "+f"(acc[i][j][0]), "+f"(acc[i][j][1]),
                          "+f"(acc[i][j][2]), "+f"(acc[i][j][3])
                        : "r"(af[i][0]), "r"(af[i][1]), "r"(af[i][2]), "r"(af[i][3]),
                          "r"(bf[j][0]), "r"(bf[j][1]));
                }
        }
    }

    // epilogue
    #pragma unroll
    for (int i = 0; i < 4; i++) {
        int r0 = bm + m_base + i * 16 + gid;
        int r1 = r0 + 8;
        #pragma unroll
        for (int j = 0; j < 4; j++) {
            int col = bn + n_base + j * 8 + qc * 2;
            #pragma unroll
            for (int h = 0; h < 2; h++) {
                int row = h ? r1 : r0;
                if (row >= Mo) continue;
                float x0 = acc[i][j][h * 2 + 0];
                float x1 = acc[i][j][h * 2 + 1];
                float* cp = C + (size_t)row * Mn + col;
                float2 r;
                if (mode == 0) {
                    r = make_float2(x0, x1);
                } else {
                    float2 p = *reinterpret_cast<const float2*>(cp);
                    if (mode == 1) {
                        r = make_float2(p.x + x0, p.y + x1);
                    } else {
                        r = make_float2(p.x + alpha * fmaxf(x0, 0.f),
                                        p.y + alpha * fmaxf(x1, 0.f));
                    }
                }
                *reinterpret_cast<float2*>(cp) = r;
            }
        }
    }
}

// ---------------- as_mat[s,t] = relu(sum_j Sxg[s,j]*Sxg[t,perm(j)] - 0.5) ----------------
__global__ void asmat_kernel() {
    __shared__ float Ps[M_];
    int s = blockIdx.x;
    for (int i = threadIdx.x; i < M_; i += blockDim.x)
        Ps[i] = g_Sxg[(size_t)s * M_ + i];
    __syncthreads();
    int warp = threadIdx.x >> 5, lane = threadIdx.x & 31;
    for (int t = warp; t < S_; t += 8) {
        float acc = 0.f;
        const float* qt = &g_Sxg[(size_t)t * M_];
        for (int j = lane; j < M_; j += 32) {
            int cp = j & 31, np = (j >> 5) & 15, lp = j >> 9;
            acc = fmaf(Ps[j], qt[cp * NL_ + np * L_ + lp], acc);
        }
        #pragma unroll
        for (int o = 16; o > 0; o >>= 1) acc += __shfl_down_sync(0xffffffffu, acc, o);
        if (lane == 0) {
            float v = acc - 0.5f;
            g_asmat[s * S_ + t] = v > 0.f ? v : 0.f;
        }
    }
}

__global__ void supmat_kernel() {
    __shared__ float Ms[S_ * S_];
    int t = threadIdx.x;
    for (int i = t; i < S_ * S_; i += blockDim.x) Ms[i] = g_asmat[i];
    __syncthreads();
    if (t >= S_) return;
    float vals[S_];
    {
        float rs = 0.f;
        for (int u = 0; u < S_; u++) rs += Ms[t * S_ + u];
        float dinv = rs > 0.f ? 1.f / rs : 0.f;
        float mx = -1e30f;
        for (int u = 0; u < S_; u++) { vals[u] = Ms[t * S_ + u] * dinv; mx = fmaxf(mx, vals[u]); }
        float se = 0.f;
        for (int u = 0; u < S_; u++) { vals[u] = expf(vals[u] - mx); se += vals[u]; }
        float inv = 1.f / se;
        for (int u = 0; u < S_; u++) g_sup0[t * S_ + u] = vals[u] * inv;
    }
    {
        float cs = 0.f;
        for (int u = 0; u < S_; u++) cs += Ms[u * S_ + t];
        float dinv = cs > 0.f ? 1.f / cs : 0.f;
        float mx = -1e30f;
        for (int u = 0; u < S_; u++) { vals[u] = Ms[u * S_ + t] * dinv; mx = fmaxf(mx, vals[u]); }
        float se = 0.f;
        for (int u = 0; u < S_; u++) { vals[u] = expf(vals[u] - mx); se += vals[u]; }
        float inv = 1.f / se;
        for (int u = 0; u < S_; u++) g_sup1[t * S_ + u] = vals[u] * inv;
    }
}

// ---------------- write outputs ----------------
__global__ void transpose_out(float* __restrict__ out) {
    const int HFsz = N_ * CO_ * V_ * L_;
    const int HCsz = N_ * CO_ * VC_ * L_;
    const int HSsz = N_ * CO_ * S_ * L_;
    int idx = blockIdx.x * blockDim.x + threadIdx.x;
    if (idx < HFsz) {
        int l = idx % L_;
        int v = (idx / L_) % V_;
        int o = (idx / (L_ * V_)) % CO_;
        int n = idx / (L_ * V_ * CO_);
        out[idx] = g_HF[(size_t)v * M_ + o * NL_ + n * L_ + l];
    } else if (idx < HFsz + HCsz) {
        int k = idx - HFsz;
        int l = k % L_;
        int w = (k / L_) % VC_;
        int o = (k / (L_ * VC_)) % CO_;
        int n = k / (L_ * VC_ * CO_);
        out[idx] = g_HC[(size_t)w * M_ + o * NL_ + n * L_ + l];
    } else if (idx < HFsz + HCsz + HSsz) {
        int k = idx - HFsz - HCsz;
        int l = k % L_;
        int s = (k / L_) % S_;
        int o = (k / (L_ * S_)) % CO_;
        int n = k / (L_ * S_ * CO_);
        out[idx] = g_HS[(size_t)s * M_ + o * NL_ + n * L_ + l];
    }
}

// ---------------- host side ----------------
static inline void launch_gemm(const void* A, const void* B, void* C,
                               int Mo, int K, int mode, float alpha) {
    dim3 grid(M_ / 128, (Mo + 127) / 128);
    gemm_tf32<<<grid, 256, SMEMF * sizeof(float)>>>(
        (const float*)A, (const float*)B, (float*)C, Mo, M_, K, mode, alpha);
}

extern "C" void kernel_launch(void* const* d_in, const int* in_sizes, int n_in,
                              void* d_out, int out_size) {
    (void)in_sizes; (void)n_in; (void)out_size;
    const float* x         = (const float*)d_in[0];
    const float* support   = (const float*)d_in[1];
    const float* support_c = (const float*)d_in[2];
    const float* acs       = (const float*)d_in[3];
    const float* afc       = (const float*)d_in[4];
    const float* W         = (const float*)d_in[5];
    const float* b         = (const float*)d_in[6];
    float* out = (float*)d_out;

    cudaFuncSetAttribute(gemm_tf32, cudaFuncAttributeMaxDynamicSharedMemorySize,
                         SMEMF * sizeof(float));

    void *pX, *pZ2, *pZ3, *pHF, *pXc, *pZc2, *pZc3, *pHC;
    void *pSxg, *pZs2, *pZs3, *pHS, *psup0, *psup1, *pacsT, *pafcT;
    cudaGetSymbolAddress(&pX, g_X);     cudaGetSymbolAddress(&pZ2, g_Z2);
    cudaGetSymbolAddress(&pZ3, g_Z3);   cudaGetSymbolAddress(&pHF, g_HF);
    cudaGetSymbolAddress(&pXc, g_Xc);   cudaGetSymbolAddress(&pZc2, g_Zc2);
    cudaGetSymbolAddress(&pZc3, g_Zc3); cudaGetSymbolAddress(&pHC, g_HC);
    cudaGetSymbolAddress(&pSxg, g_Sxg); cudaGetSymbolAddress(&pZs2, g_Zs2);
    cudaGetSymbolAddress(&pZs3, g_Zs3); cudaGetSymbolAddress(&pHS, g_HS);
    cudaGetSymbolAddress(&psup0, g_sup0); cudaGetSymbolAddress(&psup1, g_sup1);
    cudaGetSymbolAddress(&pacsT, g_acsT); cudaGetSymbolAddress(&pafcT, g_afcT);

    // 1. layout transposes
    transpose_in<<<(N_ * C_ * V_ * L_ + 255) / 256, 256>>>(x);
    transpose_acs<<<(S_ * VC_ + 255) / 256, 256>>>(acs);
    transpose_afc<<<(VC_ * V_ + 255) / 256, 256>>>(afc);

    // 2. fine level
    chanmix<<<V_, 192>>>((const float*)pX, W, b, (float*)pHF, (float*)pZ2, (float*)pZ3);
    launch_gemm(support,                   pZ2, pHF, V_, V_, 1, 1.f);
    launch_gemm(support + (size_t)V_ * V_, pZ3, pHF, V_, V_, 1, 1.f);

    // 3. coarse level
    launch_gemm(afc, pX, pXc, VC_, V_, 0, 1.f);
    chanmix<<<VC_, 192>>>((const float*)pXc, W, b, (float*)pHC, (float*)pZc2, (float*)pZc3);
    launch_gemm(support_c,                     pZc2, pHC, VC_, VC_, 1, 1.f);
    launch_gemm(support_c + (size_t)VC_ * VC_, pZc3, pHC, VC_, VC_, 1, 1.f);

    // 4. super level input
    launch_gemm(acs, pXc, pSxg, S_, VC_, 0, 1.f);

    // 5. data-dependent super supports (exact fp32)
    asmat_kernel<<<S_, 256>>>();
    supmat_kernel<<<1, 64>>>();

    // 6. super gcn
    chanmix<<<S_, 192>>>((const float*)pSxg, W, b, (float*)pHS, (float*)pZs2, (float*)pZs3);
    launch_gemm(psup0, pZs2, pHS, S_, S_, 1, 1.f);
    launch_gemm(psup1, pZs3, pHS, S_, S_, 1, 1.f);

    // 7. hierarchical residual fusions (order matters)
    launch_gemm(pacsT, pHS, pHC, VC_, S_,  2, N1F);
    launch_gemm(pafcT, pHC, pHF, V_,  VC_, 2, N2F);
    launch_gemm(afc,   pHF, pHC, VC_, V_,  2, N3F);
    launch_gemm(acs,   pHC, pHS, S_,  VC_, 2, N4F);

    // 8. write out
    transpose_out<<<(N_ * CO_ * (V_ + VC_ + S_) * L_ + 255) / 256, 256>>>(out);
}

// round 7
// speedup vs baseline: 2.6855x; 1.1227x over previous
#include <cuda_runtime.h>
#include <cstdint>
#include <math.h>

// dims
#define N_  16
#define C_  32
#define V_  2048
#define VC_ 256
#define S_  64
#define L_  12
#define CO_ 32
#define NL_ 192        // N_*L_
#define M_  6144       // C_*N_*L_  (column index m = c*192 + n*12 + l)

// residual fusion scales
#define N1F 0.8f
#define N2F 0.2f
#define N3F 0.2f
#define N4F 0.2f

// ---------------- scratch (static device arrays; no allocs allowed) ----------------
__device__ float g_X  [V_  * M_];
__device__ float g_Z2 [V_  * M_];
__device__ float g_Z3 [V_  * M_];
__device__ float g_HF [V_  * M_];
__device__ float g_Xc [VC_ * M_];
__device__ float g_Zc2[VC_ * M_];
__device__ float g_Zc3[VC_ * M_];
__device__ float g_HC [VC_ * M_];
__device__ float g_Sxg[S_  * M_];
__device__ float g_Zs2[S_  * M_];
__device__ float g_Zs3[S_  * M_];
__device__ float g_HS [S_  * M_];
__device__ float g_asmat[S_ * S_];
__device__ float g_sup0 [S_ * S_];
__device__ float g_sup1 [S_ * S_];
__device__ float g_acsT [S_ * VC_];
__device__ float g_afcT [VC_ * V_];

__device__ __forceinline__ unsigned pack_h2(float lo, float hi) {
    unsigned r;
    asm("cvt.rn.f16x2.f32 %0, %1, %2;" : "=r"(r) : "f"(hi), "f"(lo));  // a->hi, b->lo
    return r;
}
__device__ __forceinline__ uint32_t smem_u32(const void* p) {
    uint32_t a;
    asm("{ .reg .u64 t; cvta.to.shared.u64 t, %1; cvt.u32.u64 %0, t; }" : "=r"(a) : "l"(p));
    return a;
}
#define CP_COMMIT() asm volatile("cp.async.commit_group;" ::: "memory")
#define CP_WAIT(n)  asm volatile("cp.async.wait_group %0;" :: "n"(n) : "memory")

// ---------------- transpose x [N,C,V,L] -> X [V, M] ----------------
__global__ void transpose_in(const float* __restrict__ x) {
    int idx = blockIdx.x * blockDim.x + threadIdx.x;
    if (idx >= N_ * C_ * V_ * L_) return;
    int l = idx % L_;
    int v = (idx / L_) % V_;
    int c = (idx / (L_ * V_)) % C_;
    int n = idx / (L_ * V_ * C_);
    g_X[(size_t)v * M_ + c * NL_ + n * L_ + l] = x[idx];
}

__global__ void transpose_acs(const float* __restrict__ acs) {
    int idx = blockIdx.x * blockDim.x + threadIdx.x;
    if (idx >= S_ * VC_) return;
    int s = idx / VC_, w = idx % VC_;
    g_acsT[idx] = acs[w * S_ + s];
}

__global__ void transpose_afc(const float* __restrict__ afc) {
    int idx = blockIdx.x * blockDim.x + threadIdx.x;
    if (idx >= VC_ * V_) return;
    int w = idx / V_, v = idx % V_;
    g_afcT[idx] = afc[(size_t)v * VC_ + w];
}

// ---------------- channel mix ----------------
__global__ void chanmix(const float* __restrict__ Xin,
                        const float* __restrict__ W,
                        const float* __restrict__ b,
                        float* __restrict__ H,
                        float* __restrict__ Z2,
                        float* __restrict__ Z3) {
    __shared__ float sX[M_];
    __shared__ float sW[32 * 96];
    __shared__ float sb[32];
    int r = blockIdx.x;
    const float* xr = Xin + (size_t)r * M_;
    for (int i = threadIdx.x; i < M_; i += 192)      sX[i] = xr[i];
    for (int i = threadIdx.x; i < 32 * 96; i += 192) sW[i] = W[i];
    if (threadIdx.x < 32) sb[threadIdx.x] = b[threadIdx.x];
    __syncthreads();
    int nl = threadIdx.x;
    float xv[32];
    #pragma unroll
    for (int c = 0; c < 32; c++) xv[c] = sX[c * NL_ + nl];
    for (int o = 0; o < 32; o++) {
        const float* wr = &sW[o * 96];
        float a0 = sb[o], a1 = 0.f, a2 = 0.f;
        #pragma unroll
        for (int c = 0; c < 32; c++) {
            float xc = xv[c];
            a0 = fmaf(wr[c],      xc, a0);
            a1 = fmaf(wr[32 + c], xc, a1);
            a2 = fmaf(wr[64 + c], xc, a2);
        }
        size_t base = (size_t)r * M_ + o * NL_ + nl;
        H[base]  = a0;
        Z2[base] = a1;
        Z3[base] = a2;
    }
}

// ---------------- TN GEMM (fp16 mma.sync m16n8k16, 4-stage cp.async) ----------------
// A: [K x Mo] k-major, B: [K x Mn] k-major, C: [Mo x Mn] row-major (fp32 in/out).
// C[mo,mn] (op) sum_k A[k,mo]*B[k,mn];  mode 0: =, 1: +=, 2: += alpha*relu
// Block tile 128x128, 8 warps of 64x32, K-chunk 16 (one k16 MMA step per chunk).
#define BK 16
#define STG 4
#define SRD 132                       // smem row stride: 2*SRD%32==8 -> conflict-free h2 frags
#define STAGE_F (BK * SRD)
#define SMEMF (2 * STG * STAGE_F)     // 67584 B
__global__ void __launch_bounds__(256, 2)
gemm_fp16(const float* __restrict__ A, const float* __restrict__ B, float* __restrict__ C,
          int Mo, int Mn, int K, int mode, float alpha) {
    extern __shared__ float sm[];
    const uint32_t sbase = smem_u32(sm);

    const int bm = blockIdx.y * 128;
    const int bn = blockIdx.x * 128;
    const int tid  = threadIdx.x;
    const int lane = tid & 31;
    const int gid  = lane >> 2;   // 0..7
    const int qc   = lane & 3;    // 0..3
    const int warp = tid >> 5;
    const int m_base = (warp >> 2) * 64;
    const int n_base = (warp & 3) * 32;

    const int lrow0 = tid >> 5;            // k-rows 0..7 (then +8)
    const int lc4   = (tid & 31) << 2;     // m-cols 0,4,...,124

    float acc[4][4][4];
    #pragma unroll
    for (int i = 0; i < 4; i++)
        #pragma unroll
        for (int j = 0; j < 4; j++)
            #pragma unroll
            for (int t = 0; t < 4; t++) acc[i][j][t] = 0.f;

    const int nch = K / BK;

    auto load_stage = [&](int chunk, int slot) {
        const int k0 = chunk * BK;
        #pragma unroll
        for (int h = 0; h < 2; h++) {
            const int row = lrow0 + h * 8;
            uint32_t da = sbase + (uint32_t)(slot * STAGE_F + row * SRD + lc4) * 4u;
            const float* ga = A + (size_t)(k0 + row) * Mo + bm + lc4;
            int sz = (bm + lc4 < Mo) ? 16 : 0;
            if (!sz) ga = A;
            asm volatile("cp.async.cg.shared.global [%0], [%1], 16, %2;"
                         :: "r"(da), "l"(ga), "r"(sz));
            uint32_t db = sbase + (uint32_t)((STG + slot) * STAGE_F + row * SRD + lc4) * 4u;
            const float* gb = B + (size_t)(k0 + row) * Mn + bn + lc4;
            asm volatile("cp.async.cg.shared.global [%0], [%1], 16;"
                         :: "r"(db), "l"(gb));
        }
    };

    #pragma unroll
    for (int s = 0; s < STG - 1; s++) {
        if (s < nch) load_stage(s, s);
        CP_COMMIT();
    }

    for (int ch = 0; ch < nch; ch++) {
        CP_WAIT(STG - 2);
        __syncthreads();

        int nx = ch + STG - 1;
        if (nx < nch) load_stage(nx, nx & (STG - 1));
        CP_COMMIT();

        const float* As = sm + (ch & (STG - 1)) * STAGE_F;
        const float* Bs = sm + (STG + (ch & (STG - 1))) * STAGE_F;

        // fragments: m16n8k16 fp16 (A row-major in k x m smem; B likewise)
        unsigned af[4][4];
        #pragma unroll
        for (int i = 0; i < 4; i++) {
            int mb = m_base + i * 16;
            const float* r0 = As + (2 * qc    ) * SRD + mb;
            const float* r1 = As + (2 * qc + 1) * SRD + mb;
            const float* r8 = As + (2 * qc + 8) * SRD + mb;
            const float* r9 = As + (2 * qc + 9) * SRD + mb;
            af[i][0] = pack_h2(r0[gid],     r1[gid]);
            af[i][1] = pack_h2(r0[gid + 8], r1[gid + 8]);
            af[i][2] = pack_h2(r8[gid],     r9[gid]);
            af[i][3] = pack_h2(r8[gid + 8], r9[gid + 8]);
        }
        unsigned bf[4][2];
        #pragma unroll
        for (int j = 0; j < 4; j++) {
            int nb = n_base + j * 8;
            bf[j][0] = pack_h2(Bs[(2 * qc    ) * SRD + nb + gid],
                               Bs[(2 * qc + 1) * SRD + nb + gid]);
            bf[j][1] = pack_h2(Bs[(2 * qc + 8) * SRD + nb + gid],
                               Bs[(2 * qc + 9) * SRD + nb + gid]);
        }
        #pragma unroll
        for (int i = 0; i < 4; i++)
            #pragma unroll
            for (int j = 0; j < 4; j++) {
                asm volatile(
                    "mma.sync.aligned.m16n8k16.row.col.f32.f16.f16.f32 "
                    "{%0,%1,%2,%3},{%4,%5,%6,%7},{%8,%9},{%0,%1,%2,%3};\n"
                    : "+f"(acc[i][j][0]), "+f"(acc[i][j][1]),
                      "+f"(acc[i][j][2]), "+f"(acc[i][j][3])
                    : "r"(af[i][0]), "r"(af[i][1]), "r"(af[i][2]), "r"(af[i][3]),
                      "r"(bf[j][0]), "r"(bf[j][1]));
            }
    }

    // epilogue (same D layout as m16n8k8)
    #pragma unroll
    for (int i = 0; i < 4; i++) {
        int r0 = bm + m_base + i * 16 + gid;
        int r1 = r0 + 8;
        #pragma unroll
        for (int j = 0; j < 4; j++) {
            int col = bn + n_base + j * 8 + qc * 2;
            #pragma unroll
            for (int h = 0; h < 2; h++) {
                int row = h ? r1 : r0;
                if (row >= Mo) continue;
                float x0 = acc[i][j][h * 2 + 0];
                float x1 = acc[i][j][h * 2 + 1];
                float* cp = C + (size_t)row * Mn + col;
                float2 r;
                if (mode == 0) {
                    r = make_float2(x0, x1);
                } else {
                    float2 p = *reinterpret_cast<const float2*>(cp);
                    if (mode == 1) {
                        r = make_float2(p.x + x0, p.y + x1);
                    } else {
                        r = make_float2(p.x + alpha * fmaxf(x0, 0.f),
                                        p.y + alpha * fmaxf(x1, 0.f));
                    }
                }
                *reinterpret_cast<float2*>(cp) = r;
            }
        }
    }
}

// ---------------- as_mat[s,t] = relu(sum_j Sxg[s,j]*Sxg[t,perm(j)] - 0.5) ----------------
__global__ void asmat_kernel() {
    __shared__ float Ps[M_];
    int s = blockIdx.x;
    for (int i = threadIdx.x; i < M_; i += blockDim.x)
        Ps[i] = g_Sxg[(size_t)s * M_ + i];
    __syncthreads();
    int warp = threadIdx.x >> 5, lane = threadIdx.x & 31;
    for (int t = warp; t < S_; t += 8) {
        float acc = 0.f;
        const float* qt = &g_Sxg[(size_t)t * M_];
        for (int j = lane; j < M_; j += 32) {
            int cp = j & 31, np = (j >> 5) & 15, lp = j >> 9;
            acc = fmaf(Ps[j], qt[cp * NL_ + np * L_ + lp], acc);
        }
        #pragma unroll
        for (int o = 16; o > 0; o >>= 1) acc += __shfl_down_sync(0xffffffffu, acc, o);
        if (lane == 0) {
            float v = acc - 0.5f;
            g_asmat[s * S_ + t] = v > 0.f ? v : 0.f;
        }
    }
}

__global__ void supmat_kernel() {
    __shared__ float Ms[S_ * S_];
    int t = threadIdx.x;
    for (int i = t; i < S_ * S_; i += blockDim.x) Ms[i] = g_asmat[i];
    __syncthreads();
    if (t >= S_) return;
    float vals[S_];
    {
        float rs = 0.f;
        for (int u = 0; u < S_; u++) rs += Ms[t * S_ + u];
        float dinv = rs > 0.f ? 1.f / rs : 0.f;
        float mx = -1e30f;
        for (int u = 0; u < S_; u++) { vals[u] = Ms[t * S_ + u] * dinv; mx = fmaxf(mx, vals[u]); }
        float se = 0.f;
        for (int u = 0; u < S_; u++) { vals[u] = expf(vals[u] - mx); se += vals[u]; }
        float inv = 1.f / se;
        for (int u = 0; u < S_; u++) g_sup0[t * S_ + u] = vals[u] * inv;
    }
    {
        float cs = 0.f;
        for (int u = 0; u < S_; u++) cs += Ms[u * S_ + t];
        float dinv = cs > 0.f ? 1.f / cs : 0.f;
        float mx = -1e30f;
        for (int u = 0; u < S_; u++) { vals[u] = Ms[u * S_ + t] * dinv; mx = fmaxf(mx, vals[u]); }
        float se = 0.f;
        for (int u = 0; u < S_; u++) { vals[u] = expf(vals[u] - mx); se += vals[u]; }
        float inv = 1.f / se;
        for (int u = 0; u < S_; u++) g_sup1[t * S_ + u] = vals[u] * inv;
    }
}

// ---------------- write outputs ----------------
__global__ void transpose_out(float* __restrict__ out) {
    const int HFsz = N_ * CO_ * V_ * L_;
    const int HCsz = N_ * CO_ * VC_ * L_;
    const int HSsz = N_ * CO_ * S_ * L_;
    int idx = blockIdx.x * blockDim.x + threadIdx.x;
    if (idx < HFsz) {
        int l = idx % L_;
        int v = (idx / L_) % V_;
        int o = (idx / (L_ * V_)) % CO_;
        int n = idx / (L_ * V_ * CO_);
        out[idx] = g_HF[(size_t)v * M_ + o * NL_ + n * L_ + l];
    } else if (idx < HFsz + HCsz) {
        int k = idx - HFsz;
        int l = k % L_;
        int w = (k / L_) % VC_;
        int o = (k / (L_ * VC_)) % CO_;
        int n = k / (L_ * VC_ * CO_);
        out[idx] = g_HC[(size_t)w * M_ + o * NL_ + n * L_ + l];
    } else if (idx < HFsz + HCsz + HSsz) {
        int k = idx - HFsz - HCsz;
        int l = k % L_;
        int s = (k / L_) % S_;
        int o = (k / (L_ * S_)) % CO_;
        int n = k / (L_ * S_ * CO_);
        out[idx] = g_HS[(size_t)s * M_ + o * NL_ + n * L_ + l];
    }
}

// ---------------- host side ----------------
static inline void launch_gemm(const void* A, const void* B, void* C,
                               int Mo, int K, int mode, float alpha) {
    dim3 grid(M_ / 128, (Mo + 127) / 128);
    gemm_fp16<<<grid, 256, SMEMF * sizeof(float)>>>(
        (const float*)A, (const float*)B, (float*)C, Mo, M_, K, mode, alpha);
}

extern "C" void kernel_launch(void* const* d_in, const int* in_sizes, int n_in,
                              void* d_out, int out_size) {
    (void)in_sizes; (void)n_in; (void)out_size;
    const float* x         = (const float*)d_in[0];
    const float* support   = (const float*)d_in[1];
    const float* support_c = (const float*)d_in[2];
    const float* acs       = (const float*)d_in[3];
    const float* afc       = (const float*)d_in[4];
    const float* W         = (const float*)d_in[5];
    const float* b         = (const float*)d_in[6];
    float* out = (float*)d_out;

    cudaFuncSetAttribute(gemm_fp16, cudaFuncAttributeMaxDynamicSharedMemorySize,
                         SMEMF * sizeof(float));

    void *pX, *pZ2, *pZ3, *pHF, *pXc, *pZc2, *pZc3, *pHC;
    void *pSxg, *pZs2, *pZs3, *pHS, *psup0, *psup1, *pacsT, *pafcT;
    cudaGetSymbolAddress(&pX, g_X);     cudaGetSymbolAddress(&pZ2, g_Z2);
    cudaGetSymbolAddress(&pZ3, g_Z3);   cudaGetSymbolAddress(&pHF, g_HF);
    cudaGetSymbolAddress(&pXc, g_Xc);   cudaGetSymbolAddress(&pZc2, g_Zc2);
    cudaGetSymbolAddress(&pZc3, g_Zc3); cudaGetSymbolAddress(&pHC, g_HC);
    cudaGetSymbolAddress(&pSxg, g_Sxg); cudaGetSymbolAddress(&pZs2, g_Zs2);
    cudaGetSymbolAddress(&pZs3, g_Zs3); cudaGetSymbolAddress(&pHS, g_HS);
    cudaGetSymbolAddress(&psup0, g_sup0); cudaGetSymbolAddress(&psup1, g_sup1);
    cudaGetSymbolAddress(&pacsT, g_acsT); cudaGetSymbolAddress(&pafcT, g_afcT);

    // 1. layout transposes
    transpose_in<<<(N_ * C_ * V_ * L_ + 255) / 256, 256>>>(x);
    transpose_acs<<<(S_ * VC_ + 255) / 256, 256>>>(acs);
    transpose_afc<<<(VC_ * V_ + 255) / 256, 256>>>(afc);

    // 2. fine level
    chanmix<<<V_, 192>>>((const float*)pX, W, b, (float*)pHF, (float*)pZ2, (float*)pZ3);
    launch_gemm(support,                   pZ2, pHF, V_, V_, 1, 1.f);
    launch_gemm(support + (size_t)V_ * V_, pZ3, pHF, V_, V_, 1, 1.f);

    // 3. coarse level
    launch_gemm(afc, pX, pXc, VC_, V_, 0, 1.f);
    chanmix<<<VC_, 192>>>((const float*)pXc, W, b, (float*)pHC, (float*)pZc2, (float*)pZc3);
    launch_gemm(support_c,                     pZc2, pHC, VC_, VC_, 1, 1.f);
    launch_gemm(support_c + (size_t)VC_ * VC_, pZc3, pHC, VC_, VC_, 1, 1.f);

    // 4. super level input
    launch_gemm(acs, pXc, pSxg, S_, VC_, 0, 1.f);

    // 5. data-dependent super supports (exact fp32)
    asmat_kernel<<<S_, 256>>>();
    supmat_kernel<<<1, 64>>>();

    // 6. super gcn
    chanmix<<<S_, 192>>>((const float*)pSxg, W, b, (float*)pHS, (float*)pZs2, (float*)pZs3);
    launch_gemm(psup0, pZs2, pHS, S_, S_, 1, 1.f);
    launch_gemm(psup1, pZs3, pHS, S_, S_, 1, 1.f);

    // 7. hierarchical residual fusions (order matters)
    launch_gemm(pacsT, pHS, pHC, VC_, S_,  2, N1F);
    launch_gemm(pafcT, pHC, pHF, V_,  VC_, 2, N2F);
    launch_gemm(afc,   pHF, pHC, VC_, V_,  2, N3F);
    launch_gemm(acs,   pHC, pHS, S_,  VC_, 2, N4F);

    // 8. write out
    transpose_out<<<(N_ * CO_ * (V_ + VC_ + S_) * L_ + 255) / 256, 256>>>(out);
}

// round 8
// speedup vs baseline: 2.9642x; 1.1038x over previous
#include <cuda_runtime.h>
#include <cstdint>
#include <math.h>

// dims
#define N_  16
#define C_  32
#define V_  2048
#define VC_ 256
#define S_  64
#define L_  12
#define CO_ 32
#define NL_ 192        // N_*L_
#define M_  6144       // C_*N_*L_  (column index m = c*192 + n*12 + l)

// residual fusion scales
#define N1F 0.8f
#define N2F 0.2f
#define N3F 0.2f
#define N4F 0.2f

// ---------------- scratch ----------------
__device__ float g_X  [V_  * M_];
__device__ float g_Z2 [V_  * M_];
__device__ float g_Z3 [V_  * M_];
__device__ float g_HF [V_  * M_];
__device__ float g_Xc [VC_ * M_];
__device__ float g_Zc2[VC_ * M_];
__device__ float g_Zc3[VC_ * M_];
__device__ float g_HC [VC_ * M_];
__device__ float g_Sxg[S_  * M_];
__device__ float g_Zs2[S_  * M_];
__device__ float g_Zs3[S_  * M_];
__device__ float g_HS [S_  * M_];
__device__ float g_asmat[S_ * S_];
__device__ float g_sup0 [S_ * S_];
__device__ float g_sup1 [S_ * S_];
__device__ float g_acsT [S_ * VC_];
__device__ float g_afcT [VC_ * V_];

__device__ __forceinline__ unsigned pack_h2(float lo, float hi) {
    unsigned r;
    asm("cvt.rn.f16x2.f32 %0, %1, %2;" : "=r"(r) : "f"(hi), "f"(lo));  // lo -> low half
    return r;
}
__device__ __forceinline__ uint32_t smem_u32(const void* p) {
    uint32_t a;
    asm("{ .reg .u64 t; cvta.to.shared.u64 t, %1; cvt.u32.u64 %0, t; }" : "=r"(a) : "l"(p));
    return a;
}
#define LDSM4T(r0, r1, r2, r3, addr) \
    asm volatile("ldmatrix.sync.aligned.m8n8.x4.trans.shared.b16 {%0,%1,%2,%3}, [%4];" \
                 : "=r"(r0), "=r"(r1), "=r"(r2), "=r"(r3) : "r"(addr))

// ---------------- transpose x [N,C,V,L] -> X [V, M] ----------------
__global__ void transpose_in(const float* __restrict__ x) {
    int idx = blockIdx.x * blockDim.x + threadIdx.x;
    if (idx >= N_ * C_ * V_ * L_) return;
    int l = idx % L_;
    int v = (idx / L_) % V_;
    int c = (idx / (L_ * V_)) % C_;
    int n = idx / (L_ * V_ * C_);
    g_X[(size_t)v * M_ + c * NL_ + n * L_ + l] = x[idx];
}

__global__ void transpose_acs(const float* __restrict__ acs) {
    int idx = blockIdx.x * blockDim.x + threadIdx.x;
    if (idx >= S_ * VC_) return;
    int s = idx / VC_, w = idx % VC_;
    g_acsT[idx] = acs[w * S_ + s];
}

__global__ void transpose_afc(const float* __restrict__ afc) {
    int idx = blockIdx.x * blockDim.x + threadIdx.x;
    if (idx >= VC_ * V_) return;
    int w = idx / V_, v = idx % V_;
    g_afcT[idx] = afc[(size_t)v * VC_ + w];
}

// ---------------- channel mix ----------------
__global__ void chanmix(const float* __restrict__ Xin,
                        const float* __restrict__ W,
                        const float* __restrict__ b,
                        float* __restrict__ H,
                        float* __restrict__ Z2,
                        float* __restrict__ Z3) {
    __shared__ float sX[M_];
    __shared__ float sW[32 * 96];
    __shared__ float sb[32];
    int r = blockIdx.x;
    const float* xr = Xin + (size_t)r * M_;
    for (int i = threadIdx.x; i < M_; i += 192)      sX[i] = xr[i];
    for (int i = threadIdx.x; i < 32 * 96; i += 192) sW[i] = W[i];
    if (threadIdx.x < 32) sb[threadIdx.x] = b[threadIdx.x];
    __syncthreads();
    int nl = threadIdx.x;
    float xv[32];
    #pragma unroll
    for (int c = 0; c < 32; c++) xv[c] = sX[c * NL_ + nl];
    for (int o = 0; o < 32; o++) {
        const float* wr = &sW[o * 96];
        float a0 = sb[o], a1 = 0.f, a2 = 0.f;
        #pragma unroll
        for (int c = 0; c < 32; c++) {
            float xc = xv[c];
            a0 = fmaf(wr[c],      xc, a0);
            a1 = fmaf(wr[32 + c], xc, a1);
            a2 = fmaf(wr[64 + c], xc, a2);
        }
        size_t base = (size_t)r * M_ + o * NL_ + nl;
        H[base]  = a0;
        Z2[base] = a1;
        Z3[base] = a2;
    }
}

// ---------------- TN GEMM (fp16 mma.sync + ldmatrix, 3-stage half smem) ----------------
// A: [K x Mo] k-major, B: [K x Mn] k-major, C: [Mo x Mn] row-major (fp32 in/out).
// C[mo,mn] (op) sum_k A[k,mo]*B[k,mn];  mode 0: =, 1: +=, 2: += alpha*relu
// Block tile 128x128, 8 warps of 64x32, K-chunk 16.
// SMEM half tiles [k=16][m=128], row 256 B, granule swizzle mg ^= (k&7).
#define STAGE_B 8192   // A 4096 + B 4096 per stage
__global__ void __launch_bounds__(256, 2)
gemm_fp16(const float* __restrict__ A, const float* __restrict__ B, float* __restrict__ C,
          int Mo, int Mn, int K, int mode, float alpha) {
    __shared__ __align__(16) char smh[3 * STAGE_B];
    const uint32_t sbase = smem_u32(smh);

    const int bm = blockIdx.y * 128;
    const int bn = blockIdx.x * 128;
    const int tid  = threadIdx.x;
    const int lane = tid & 31;
    const int warp = tid >> 5;
    const int m_base = (warp >> 2) * 64;
    const int n_base = (warp & 3) * 32;

    // loader indices: thread covers k-rows (warp, warp+8), m cols lc4..lc4+3
    const int lrow0 = warp;                 // 0..7
    const int lc4   = (tid & 31) << 2;      // 0,4,...,124
    const int mg    = lc4 >> 3;             // granule 0..15
    const int hoff  = (lc4 & 7) * 2;        // 0 or 8 bytes within granule

    // ldmatrix per-lane address offsets (within a stage's A or B tile)
    // A: group g = lane>>3: g0=(k0-7, m mb+0-7)->a0, g1=(k0-7, mb+8-15)->a1,
    //    g2=(k8-15, mb+0-7)->a2, g3=(k8-15, mb+8-15)->a3
    const int gA  = lane >> 3;
    const int krA = (lane & 7) | ((gA & 2) << 2);
    int offA[4];
    #pragma unroll
    for (int i = 0; i < 4; i++) {
        int mgA = ((m_base + i * 16) >> 3) + (gA & 1);
        offA[i] = krA * 256 + ((mgA ^ (krA & 7)) << 4);
    }
    // B: g0=(k0-7, nb)->bj0[0], g1=(k8-15, nb)->bj0[1], g2=(k0-7, nb+8)->bj1[0], g3=(k8-15, nb+8)->bj1[1]
    const int gB  = lane >> 3;
    const int krB = (lane & 7) | ((gB & 1) << 3);
    int offB[2];
    #pragma unroll
    for (int jp = 0; jp < 2; jp++) {
        int ngB = ((n_base + jp * 16) >> 3) + (gB >> 1);
        offB[jp] = krB * 256 + ((ngB ^ (krB & 7)) << 4);
    }

    float acc[4][4][4];
    #pragma unroll
    for (int i = 0; i < 4; i++)
        #pragma unroll
        for (int j = 0; j < 4; j++)
            #pragma unroll
            for (int t = 0; t < 4; t++) acc[i][j][t] = 0.f;

    const int nch = K >> 4;
    float4 va[2], vb[2];

    auto load_regs = [&](int ch) {
        if (ch >= nch) return;
        const int k0 = ch << 4;
        const bool aok = (bm + lc4 < Mo);
        #pragma unroll
        for (int h = 0; h < 2; h++) {
            const int kr = k0 + lrow0 + h * 8;
            va[h] = aok ? *reinterpret_cast<const float4*>(A + (size_t)kr * Mo + bm + lc4)
                        : make_float4(0.f, 0.f, 0.f, 0.f);
            vb[h] = *reinterpret_cast<const float4*>(B + (size_t)kr * Mn + bn + lc4);
        }
    };
    auto sts_regs = [&](int ch) {
        if (ch >= nch) return;
        char* stg = smh + (ch % 3) * STAGE_B;
        #pragma unroll
        for (int h = 0; h < 2; h++) {
            const int kr = lrow0 + h * 8;
            const int gsw = (mg ^ (kr & 7)) << 4;
            uint2 ua = make_uint2(pack_h2(va[h].x, va[h].y), pack_h2(va[h].z, va[h].w));
            *reinterpret_cast<uint2*>(stg + kr * 256 + gsw + hoff) = ua;
            uint2 ub = make_uint2(pack_h2(vb[h].x, vb[h].y), pack_h2(vb[h].z, vb[h].w));
            *reinterpret_cast<uint2*>(stg + 4096 + kr * 256 + gsw + hoff) = ub;
        }
    };

    // prologue: smem gets chunk 0; regs get chunk 1
    load_regs(0);
    sts_regs(0);
    load_regs(1);

    for (int ch = 0; ch < nch; ch++) {
        sts_regs(ch + 1);
        load_regs(ch + 2);
        __syncthreads();

        const uint32_t a_s = sbase + (uint32_t)((ch % 3) * STAGE_B);
        const uint32_t b_s = a_s + 4096u;

        unsigned af[4][4];
        #pragma unroll
        for (int i = 0; i < 4; i++)
            LDSM4T(af[i][0], af[i][1], af[i][2], af[i][3], a_s + offA[i]);
        unsigned bf[4][2];
        #pragma unroll
        for (int jp = 0; jp < 2; jp++) {
            unsigned r0, r1, r2, r3;
            LDSM4T(r0, r1, r2, r3, b_s + offB[jp]);
            bf[jp * 2][0] = r0;  bf[jp * 2][1] = r1;
            bf[jp * 2 + 1][0] = r2;  bf[jp * 2 + 1][1] = r3;
        }

        #pragma unroll
        for (int i = 0; i < 4; i++)
            #pragma unroll
            for (int j = 0; j < 4; j++) {
                asm volatile(
                    "mma.sync.aligned.m16n8k16.row.col.f32.f16.f16.f32 "
                    "{%0,%1,%2,%3},{%4,%5,%6,%7},{%8,%9},{%0,%1,%2,%3};\n"
                    : "+f"(acc[i][j][0]), "+f"(acc[i][j][1]),
                      "+f"(acc[i][j][2]), "+f"(acc[i][j][3])
                    : "r"(af[i][0]), "r"(af[i][1]), "r"(af[i][2]), "r"(af[i][3]),
                      "r"(bf[j][0]), "r"(bf[j][1]));
            }
        __syncthreads();
    }

    // epilogue
    const int gid = lane >> 2;
    const int qc  = lane & 3;
    #pragma unroll
    for (int i = 0; i < 4; i++) {
        int r0 = bm + m_base + i * 16 + gid;
        int r1 = r0 + 8;
        #pragma unroll
        for (int j = 0; j < 4; j++) {
            int col = bn + n_base + j * 8 + qc * 2;
            #pragma unroll
            for (int h = 0; h < 2; h++) {
                int row = h ? r1 : r0;
                if (row >= Mo) continue;
                float x0 = acc[i][j][h * 2 + 0];
                float x1 = acc[i][j][h * 2 + 1];
                float* cp = C + (size_t)row * Mn + col;
                float2 r;
                if (mode == 0) {
                    r = make_float2(x0, x1);
                } else {
                    float2 p = *reinterpret_cast<const float2*>(cp);
                    if (mode == 1) {
                        r = make_float2(p.x + x0, p.y + x1);
                    } else {
                        r = make_float2(p.x + alpha * fmaxf(x0, 0.f),
                                        p.y + alpha * fmaxf(x1, 0.f));
                    }
                }
                *reinterpret_cast<float2*>(cp) = r;
            }
        }
    }
}

// ---------------- as_mat[s,t] = relu(sum_j Sxg[s,j]*Sxg[t,perm(j)] - 0.5) ----------------
__global__ void asmat_kernel() {
    __shared__ float Ps[M_];
    int s = blockIdx.x;
    for (int i = threadIdx.x; i < M_; i += blockDim.x)
        Ps[i] = g_Sxg[(size_t)s * M_ + i];
    __syncthreads();
    int warp = threadIdx.x >> 5, lane = threadIdx.x & 31;
    for (int t = warp; t < S_; t += 8) {
        float acc = 0.f;
        const float* qt = &g_Sxg[(size_t)t * M_];
        for (int j = lane; j < M_; j += 32) {
            int cp = j & 31, np = (j >> 5) & 15, lp = j >> 9;
            acc = fmaf(Ps[j], qt[cp * NL_ + np * L_ + lp], acc);
        }
        #pragma unroll
        for (int o = 16; o > 0; o >>= 1) acc += __shfl_down_sync(0xffffffffu, acc, o);
        if (lane == 0) {
            float v = acc - 0.5f;
            g_asmat[s * S_ + t] = v > 0.f ? v : 0.f;
        }
    }
}

__global__ void supmat_kernel() {
    __shared__ float Ms[S_ * S_];
    int t = threadIdx.x;
    for (int i = t; i < S_ * S_; i += blockDim.x) Ms[i] = g_asmat[i];
    __syncthreads();
    if (t >= S_) return;
    float vals[S_];
    {
        float rs = 0.f;
        for (int u = 0; u < S_; u++) rs += Ms[t * S_ + u];
        float dinv = rs > 0.f ? 1.f / rs : 0.f;
        float mx = -1e30f;
        for (int u = 0; u < S_; u++) { vals[u] = Ms[t * S_ + u] * dinv; mx = fmaxf(mx, vals[u]); }
        float se = 0.f;
        for (int u = 0; u < S_; u++) { vals[u] = expf(vals[u] - mx); se += vals[u]; }
        float inv = 1.f / se;
        for (int u = 0; u < S_; u++) g_sup0[t * S_ + u] = vals[u] * inv;
    }
    {
        float cs = 0.f;
        for (int u = 0; u < S_; u++) cs += Ms[u * S_ + t];
        float dinv = cs > 0.f ? 1.f / cs : 0.f;
        float mx = -1e30f;
        for (int u = 0; u < S_; u++) { vals[u] = Ms[u * S_ + t] * dinv; mx = fmaxf(mx, vals[u]); }
        float se = 0.f;
        for (int u = 0; u < S_; u++) { vals[u] = expf(vals[u] - mx); se += vals[u]; }
        float inv = 1.f / se;
        for (int u = 0; u < S_; u++) g_sup1[t * S_ + u] = vals[u] * inv;
    }
}

// ---------------- write outputs ----------------
__global__ void transpose_out(float* __restrict__ out) {
    const int HFsz = N_ * CO_ * V_ * L_;
    const int HCsz = N_ * CO_ * VC_ * L_;
    const int HSsz = N_ * CO_ * S_ * L_;
    int idx = blockIdx.x * blockDim.x + threadIdx.x;
    if (idx < HFsz) {
        int l = idx % L_;
        int v = (idx / L_) % V_;
        int o = (idx / (L_ * V_)) % CO_;
        int n = idx / (L_ * V_ * CO_);
        out[idx] = g_HF[(size_t)v * M_ + o * NL_ + n * L_ + l];
    } else if (idx < HFsz + HCsz) {
        int k = idx - HFsz;
        int l = k % L_;
        int w = (k / L_) % VC_;
        int o = (k / (L_ * VC_)) % CO_;
        int n = k / (L_ * VC_ * CO_);
        out[idx] = g_HC[(size_t)w * M_ + o * NL_ + n * L_ + l];
    } else if (idx < HFsz + HCsz + HSsz) {
        int k = idx - HFsz - HCsz;
        int l = k % L_;
        int s = (k / L_) % S_;
        int o = (k / (L_ * S_)) % CO_;
        int n = k / (L_ * S_ * CO_);
        out[idx] = g_HS[(size_t)s * M_ + o * NL_ + n * L_ + l];
    }
}

// ---------------- host side ----------------
static inline void launch_gemm(const void* A, const void* B, void* C,
                               int Mo, int K, int mode, float alpha) {
    dim3 grid(M_ / 128, (Mo + 127) / 128);
    gemm_fp16<<<grid, 256>>>((const float*)A, (const float*)B, (float*)C,
                             Mo, M_, K, mode, alpha);
}

extern "C" void kernel_launch(void* const* d_in, const int* in_sizes, int n_in,
                              void* d_out, int out_size) {
    (void)in_sizes; (void)n_in; (void)out_size;
    const float* x         = (const float*)d_in[0];
    const float* support   = (const float*)d_in[1];
    const float* support_c = (const float*)d_in[2];
    const float* acs       = (const float*)d_in[3];
    const float* afc       = (const float*)d_in[4];
    const float* W         = (const float*)d_in[5];
    const float* b         = (const float*)d_in[6];
    float* out = (float*)d_out;

    void *pX, *pZ2, *pZ3, *pHF, *pXc, *pZc2, *pZc3, *pHC;
    void *pSxg, *pZs2, *pZs3, *pHS, *psup0, *psup1, *pacsT, *pafcT;
    cudaGetSymbolAddress(&pX, g_X);     cudaGetSymbolAddress(&pZ2, g_Z2);
    cudaGetSymbolAddress(&pZ3, g_Z3);   cudaGetSymbolAddress(&pHF, g_HF);
    cudaGetSymbolAddress(&pXc, g_Xc);   cudaGetSymbolAddress(&pZc2, g_Zc2);
    cudaGetSymbolAddress(&pZc3, g_Zc3); cudaGetSymbolAddress(&pHC, g_HC);
    cudaGetSymbolAddress(&pSxg, g_Sxg); cudaGetSymbolAddress(&pZs2, g_Zs2);
    cudaGetSymbolAddress(&pZs3, g_Zs3); cudaGetSymbolAddress(&pHS, g_HS);
    cudaGetSymbolAddress(&psup0, g_sup0); cudaGetSymbolAddress(&psup1, g_sup1);
    cudaGetSymbolAddress(&pacsT, g_acsT); cudaGetSymbolAddress(&pafcT, g_afcT);

    // 1. layout transposes
    transpose_in<<<(N_ * C_ * V_ * L_ + 255) / 256, 256>>>(x);
    transpose_acs<<<(S_ * VC_ + 255) / 256, 256>>>(acs);
    transpose_afc<<<(VC_ * V_ + 255) / 256, 256>>>(afc);

    // 2. fine level
    chanmix<<<V_, 192>>>((const float*)pX, W, b, (float*)pHF, (float*)pZ2, (float*)pZ3);
    launch_gemm(support,                   pZ2, pHF, V_, V_, 1, 1.f);
    launch_gemm(support + (size_t)V_ * V_, pZ3, pHF, V_, V_, 1, 1.f);

    // 3. coarse level
    launch_gemm(afc, pX, pXc, VC_, V_, 0, 1.f);
    chanmix<<<VC_, 192>>>((const float*)pXc, W, b, (float*)pHC, (float*)pZc2, (float*)pZc3);
    launch_gemm(support_c,                     pZc2, pHC, VC_, VC_, 1, 1.f);
    launch_gemm(support_c + (size_t)VC_ * VC_, pZc3, pHC, VC_, VC_, 1, 1.f);

    // 4. super level input
    launch_gemm(acs, pXc, pSxg, S_, VC_, 0, 1.f);

    // 5. data-dependent super supports (exact fp32)
    asmat_kernel<<<S_, 256>>>();
    supmat_kernel<<<1, 64>>>();

    // 6. super gcn
    chanmix<<<S_, 192>>>((const float*)pSxg, W, b, (float*)pHS, (float*)pZs2, (float*)pZs3);
    launch_gemm(psup0, pZs2, pHS, S_, S_, 1, 1.f);
    launch_gemm(psup1, pZs3, pHS, S_, S_, 1, 1.f);

    // 7. hierarchical residual fusions (order matters)
    launch_gemm(pacsT, pHS, pHC, VC_, S_,  2, N1F);
    launch_gemm(pafcT, pHC, pHF, V_,  VC_, 2, N2F);
    launch_gemm(afc,   pHF, pHC, VC_, V_,  2, N3F);
    launch_gemm(acs,   pHC, pHS, S_,  VC_, 2, N4F);

    // 8. write out
    transpose_out<<<(N_ * CO_ * (V_ + VC_ + S_) * L_ + 255) / 256, 256>>>(out);
}

// round 9
// speedup vs baseline: 3.1015x; 1.0463x over previous
#include <cuda_runtime.h>
#include <cstdint>
#include <math.h>

// dims
#define N_  16
#define C_  32
#define V_  2048
#define VC_ 256
#define S_  64
#define L_  12
#define CO_ 32
#define NL_ 192        // N_*L_
#define M_  6144       // C_*N_*L_  (column index m = c*192 + n*12 + l)

// residual fusion scales
#define N1F 0.8f
#define N2F 0.2f
#define N3F 0.2f
#define N4F 0.2f

// ---------------- scratch ----------------
__device__ float g_X   [V_  * M_];
__device__ float g_Z23 [2 * V_  * M_];   // [Z2; Z3] contiguous (K-concat for merged GEMM)
__device__ float g_HF  [V_  * M_];
__device__ float g_Xc  [VC_ * M_];
__device__ float g_Zc23[2 * VC_ * M_];
__device__ float g_HC  [VC_ * M_];
__device__ float g_Sxg [S_  * M_];
__device__ float g_Zs23[2 * S_  * M_];
__device__ float g_HS  [S_  * M_];
__device__ float g_asmat[S_ * S_];
__device__ float g_sup01[2 * S_ * S_];   // [sup0; sup1]
__device__ float g_acsT [S_ * VC_];
__device__ float g_afcT [VC_ * V_];

__device__ __forceinline__ unsigned pack_h2(float lo, float hi) {
    unsigned r;
    asm("cvt.rn.f16x2.f32 %0, %1, %2;" : "=r"(r) : "f"(hi), "f"(lo));  // lo -> low half
    return r;
}
__device__ __forceinline__ uint32_t smem_u32(const void* p) {
    uint32_t a;
    asm("{ .reg .u64 t; cvta.to.shared.u64 t, %1; cvt.u32.u64 %0, t; }" : "=r"(a) : "l"(p));
    return a;
}
#define LDSM4T(r0, r1, r2, r3, addr) \
    asm volatile("ldmatrix.sync.aligned.m8n8.x4.trans.shared.b16 {%0,%1,%2,%3}, [%4];" \
                 : "=r"(r0), "=r"(r1), "=r"(r2), "=r"(r3) : "r"(addr))

// ---------------- transpose x [N,C,V,L] -> X [V, M] ----------------
__global__ void transpose_in(const float* __restrict__ x) {
    int idx = blockIdx.x * blockDim.x + threadIdx.x;
    if (idx >= N_ * C_ * V_ * L_) return;
    int l = idx % L_;
    int v = (idx / L_) % V_;
    int c = (idx / (L_ * V_)) % C_;
    int n = idx / (L_ * V_ * C_);
    g_X[(size_t)v * M_ + c * NL_ + n * L_ + l] = x[idx];
}

__global__ void transpose_acs(const float* __restrict__ acs) {
    int idx = blockIdx.x * blockDim.x + threadIdx.x;
    if (idx >= S_ * VC_) return;
    int s = idx / VC_, w = idx % VC_;
    g_acsT[idx] = acs[w * S_ + s];
}

__global__ void transpose_afc(const float* __restrict__ afc) {
    int idx = blockIdx.x * blockDim.x + threadIdx.x;
    if (idx >= VC_ * V_) return;
    int w = idx / V_, v = idx % V_;
    g_afcT[idx] = afc[(size_t)v * VC_ + w];
}

// ---------------- channel mix (no sX staging; float4 broadcast W) ----------------
__global__ void chanmix(const float* __restrict__ Xin,
                        const float* __restrict__ W,
                        const float* __restrict__ b,
                        float* __restrict__ H,
                        float* __restrict__ Z2,
                        float* __restrict__ Z3) {
    __shared__ float4 sW[32 * 24];   // [o][24] float4 view of [o][96]
    __shared__ float  sb[32];
    int r = blockIdx.x;
    const float* xr = Xin + (size_t)r * M_;
    for (int i = threadIdx.x; i < 32 * 24; i += 192)
        sW[i] = reinterpret_cast<const float4*>(W)[i];
    if (threadIdx.x < 32) sb[threadIdx.x] = b[threadIdx.x];
    __syncthreads();

    int nl = threadIdx.x;  // 0..191
    float xv[32];
    #pragma unroll
    for (int c = 0; c < 32; c++) xv[c] = xr[c * NL_ + nl];   // coalesced per c

    for (int o = 0; o < 32; o++) {
        const float4* wr = &sW[o * 24];
        float a0 = sb[o], a1 = 0.f, a2 = 0.f;
        #pragma unroll
        for (int c4 = 0; c4 < 8; c4++) {
            float4 w0 = wr[c4];        // W1[o, 4c4..]
            float4 w1 = wr[8 + c4];    // W2
            float4 w2 = wr[16 + c4];   // W3
            float x0 = xv[c4 * 4], x1 = xv[c4 * 4 + 1], x2 = xv[c4 * 4 + 2], x3 = xv[c4 * 4 + 3];
            a0 = fmaf(w0.x, x0, fmaf(w0.y, x1, fmaf(w0.z, x2, fmaf(w0.w, x3, a0))));
            a1 = fmaf(w1.x, x0, fmaf(w1.y, x1, fmaf(w1.z, x2, fmaf(w1.w, x3, a1))));
            a2 = fmaf(w2.x, x0, fmaf(w2.y, x1, fmaf(w2.z, x2, fmaf(w2.w, x3, a2))));
        }
        size_t base = (size_t)r * M_ + o * NL_ + nl;
        H[base]  = a0;
        Z2[base] = a1;
        Z3[base] = a2;
    }
}

// ---------------- TN GEMM (fp16 mma.sync + ldmatrix, 3-stage, 1 sync/chunk) ----------
// A: [K x Mo] k-major, B: [K x Mn] k-major, C: [Mo x Mn] row-major (fp32 in/out).
// C[mo,mn] (op) sum_k A[k,mo]*B[k,mn];  mode 0: =, 1: +=, 2: += alpha*relu
// Block tile 128x128, 8 warps of 64x32, K-chunk 16.
#define STAGE_B 8192   // A 4096 + B 4096 per stage
__global__ void __launch_bounds__(256, 2)
gemm_fp16(const float* __restrict__ A, const float* __restrict__ B, float* __restrict__ C,
          int Mo, int Mn, int K, int mode, float alpha) {
    __shared__ __align__(16) char smh[3 * STAGE_B];
    const uint32_t sbase = smem_u32(smh);

    const int bm = blockIdx.y * 128;
    const int bn = blockIdx.x * 128;
    const int tid  = threadIdx.x;
    const int lane = tid & 31;
    const int warp = tid >> 5;
    const int m_base = (warp >> 2) * 64;
    const int n_base = (warp & 3) * 32;

    const int lrow0 = warp;                 // k-rows warp, warp+8
    const int lc4   = (tid & 31) << 2;      // m cols 0,4,...,124
    const int mg    = lc4 >> 3;
    const int hoff  = (lc4 & 7) * 2;

    const int gA  = lane >> 3;
    const int krA = (lane & 7) | ((gA & 2) << 2);
    int offA[4];
    #pragma unroll
    for (int i = 0; i < 4; i++) {
        int mgA = ((m_base + i * 16) >> 3) + (gA & 1);
        offA[i] = krA * 256 + ((mgA ^ (krA & 7)) << 4);
    }
    const int gB  = lane >> 3;
    const int krB = (lane & 7) | ((gB & 1) << 3);
    int offB[2];
    #pragma unroll
    for (int jp = 0; jp < 2; jp++) {
        int ngB = ((n_base + jp * 16) >> 3) + (gB >> 1);
        offB[jp] = krB * 256 + ((ngB ^ (krB & 7)) << 4);
    }

    float acc[4][4][4];
    #pragma unroll
    for (int i = 0; i < 4; i++)
        #pragma unroll
        for (int j = 0; j < 4; j++)
            #pragma unroll
            for (int t = 0; t < 4; t++) acc[i][j][t] = 0.f;

    const int nch = K >> 4;
    float4 va[2], vb[2];

    auto load_regs = [&](int ch) {
        if (ch >= nch) return;
        const int k0 = ch << 4;
        const bool aok = (bm + lc4 < Mo);
        #pragma unroll
        for (int h = 0; h < 2; h++) {
            const int kr = k0 + lrow0 + h * 8;
            va[h] = aok ? *reinterpret_cast<const float4*>(A + (size_t)kr * Mo + bm + lc4)
                        : make_float4(0.f, 0.f, 0.f, 0.f);
            vb[h] = *reinterpret_cast<const float4*>(B + (size_t)kr * Mn + bn + lc4);
        }
    };
    auto sts_regs = [&](int ch) {
        if (ch >= nch) return;
        char* stg = smh + (ch % 3) * STAGE_B;
        #pragma unroll
        for (int h = 0; h < 2; h++) {
            const int kr = lrow0 + h * 8;
            const int gsw = (mg ^ (kr & 7)) << 4;
            uint2 ua = make_uint2(pack_h2(va[h].x, va[h].y), pack_h2(va[h].z, va[h].w));
            *reinterpret_cast<uint2*>(stg + kr * 256 + gsw + hoff) = ua;
            uint2 ub = make_uint2(pack_h2(vb[h].x, vb[h].y), pack_h2(vb[h].z, vb[h].w));
            *reinterpret_cast<uint2*>(stg + 4096 + kr * 256 + gsw + hoff) = ub;
        }
    };

    // prologue: smem gets chunk 0; regs hold chunk 1
    load_regs(0);
    sts_regs(0);
    load_regs(1);

    for (int ch = 0; ch < nch; ch++) {
        sts_regs(ch + 1);        // writes stage (ch+1)%3; last read at iter ch-2, ordered by sync(ch-1)
        load_regs(ch + 2);
        __syncthreads();         // single barrier per chunk

        const uint32_t a_s = sbase + (uint32_t)((ch % 3) * STAGE_B);
        const uint32_t b_s = a_s + 4096u;

        unsigned af[4][4];
        #pragma unroll
        for (int i = 0; i < 4; i++)
            LDSM4T(af[i][0], af[i][1], af[i][2], af[i][3], a_s + offA[i]);
        unsigned bf[4][2];
        #pragma unroll
        for (int jp = 0; jp < 2; jp++) {
            unsigned r0, r1, r2, r3;
            LDSM4T(r0, r1, r2, r3, b_s + offB[jp]);
            bf[jp * 2][0] = r0;  bf[jp * 2][1] = r1;
            bf[jp * 2 + 1][0] = r2;  bf[jp * 2 + 1][1] = r3;
        }

        #pragma unroll
        for (int i = 0; i < 4; i++)
            #pragma unroll
            for (int j = 0; j < 4; j++) {
                asm volatile(
                    "mma.sync.aligned.m16n8k16.row.col.f32.f16.f16.f32 "
                    "{%0,%1,%2,%3},{%4,%5,%6,%7},{%8,%9},{%0,%1,%2,%3};\n"
                    : "+f"(acc[i][j][0]), "+f"(acc[i][j][1]),
                      "+f"(acc[i][j][2]), "+f"(acc[i][j][3])
                    : "r"(af[i][0]), "r"(af[i][1]), "r"(af[i][2]), "r"(af[i][3]),
                      "r"(bf[j][0]), "r"(bf[j][1]));
            }
    }

    // epilogue
    const int gid = lane >> 2;
    const int qc  = lane & 3;
    #pragma unroll
    for (int i = 0; i < 4; i++) {
        int r0 = bm + m_base + i * 16 + gid;
        int r1 = r0 + 8;
        #pragma unroll
        for (int j = 0; j < 4; j++) {
            int col = bn + n_base + j * 8 + qc * 2;
            #pragma unroll
            for (int h = 0; h < 2; h++) {
                int row = h ? r1 : r0;
                if (row >= Mo) continue;
                float x0 = acc[i][j][h * 2 + 0];
                float x1 = acc[i][j][h * 2 + 1];
                float* cp = C + (size_t)row * Mn + col;
                float2 r;
                if (mode == 0) {
                    r = make_float2(x0, x1);
                } else {
                    float2 p = *reinterpret_cast<const float2*>(cp);
                    if (mode == 1) {
                        r = make_float2(p.x + x0, p.y + x1);
                    } else {
                        r = make_float2(p.x + alpha * fmaxf(x0, 0.f),
                                        p.y + alpha * fmaxf(x1, 0.f));
                    }
                }
                *reinterpret_cast<float2*>(cp) = r;
            }
        }
    }
}

// ---------------- as_mat[s,t] = relu(sum_j Sxg[s,j]*Sxg[t,perm(j)] - 0.5) ----------------
__global__ void asmat_kernel() {
    __shared__ float Ps[M_];
    int s = blockIdx.x;
    for (int i = threadIdx.x; i < M_; i += blockDim.x)
        Ps[i] = g_Sxg[(size_t)s * M_ + i];
    __syncthreads();
    int warp = threadIdx.x >> 5, lane = threadIdx.x & 31;
    for (int t = warp; t < S_; t += 8) {
        float acc = 0.f;
        const float* qt = &g_Sxg[(size_t)t * M_];
        for (int j = lane; j < M_; j += 32) {
            int cp = j & 31, np = (j >> 5) & 15, lp = j >> 9;
            acc = fmaf(Ps[j], qt[cp * NL_ + np * L_ + lp], acc);
        }
        #pragma unroll
        for (int o = 16; o > 0; o >>= 1) acc += __shfl_down_sync(0xffffffffu, acc, o);
        if (lane == 0) {
            float v = acc - 0.5f;
            g_asmat[s * S_ + t] = v > 0.f ? v : 0.f;
        }
    }
}

// ---------------- sup0 / sup1 -> contiguous g_sup01 halves ----------------
__global__ void supmat_kernel() {
    __shared__ float Ms[S_ * S_];
    int t = threadIdx.x;
    for (int i = t; i < S_ * S_; i += blockDim.x) Ms[i] = g_asmat[i];
    __syncthreads();
    if (t >= S_) return;
    float vals[S_];
    {
        float rs = 0.f;
        for (int u = 0; u < S_; u++) rs += Ms[t * S_ + u];
        float dinv = rs > 0.f ? 1.f / rs : 0.f;
        float mx = -1e30f;
        for (int u = 0; u < S_; u++) { vals[u] = Ms[t * S_ + u] * dinv; mx = fmaxf(mx, vals[u]); }
        float se = 0.f;
        for (int u = 0; u < S_; u++) { vals[u] = expf(vals[u] - mx); se += vals[u]; }
        float inv = 1.f / se;
        for (int u = 0; u < S_; u++) g_sup01[t * S_ + u] = vals[u] * inv;
    }
    {
        float cs = 0.f;
        for (int u = 0; u < S_; u++) cs += Ms[u * S_ + t];
        float dinv = cs > 0.f ? 1.f / cs : 0.f;
        float mx = -1e30f;
        for (int u = 0; u < S_; u++) { vals[u] = Ms[u * S_ + t] * dinv; mx = fmaxf(mx, vals[u]); }
        float se = 0.f;
        for (int u = 0; u < S_; u++) { vals[u] = expf(vals[u] - mx); se += vals[u]; }
        float inv = 1.f / se;
        for (int u = 0; u < S_; u++) g_sup01[S_ * S_ + t * S_ + u] = vals[u] * inv;
    }
}

// ---------------- write outputs ----------------
__global__ void transpose_out(float* __restrict__ out) {
    const int HFsz = N_ * CO_ * V_ * L_;
    const int HCsz = N_ * CO_ * VC_ * L_;
    const int HSsz = N_ * CO_ * S_ * L_;
    int idx = blockIdx.x * blockDim.x + threadIdx.x;
    if (idx < HFsz) {
        int l = idx % L_;
        int v = (idx / L_) % V_;
        int o = (idx / (L_ * V_)) % CO_;
        int n = idx / (L_ * V_ * CO_);
        out[idx] = g_HF[(size_t)v * M_ + o * NL_ + n * L_ + l];
    } else if (idx < HFsz + HCsz) {
        int k = idx - HFsz;
        int l = k % L_;
        int w = (k / L_) % VC_;
        int o = (k / (L_ * VC_)) % CO_;
        int n = k / (L_ * VC_ * CO_);
        out[idx] = g_HC[(size_t)w * M_ + o * NL_ + n * L_ + l];
    } else if (idx < HFsz + HCsz + HSsz) {
        int k = idx - HFsz - HCsz;
        int l = k % L_;
        int s = (k / L_) % S_;
        int o = (k / (L_ * S_)) % CO_;
        int n = k / (L_ * S_ * CO_);
        out[idx] = g_HS[(size_t)s * M_ + o * NL_ + n * L_ + l];
    }
}

// ---------------- host side ----------------
static inline void launch_gemm(const void* A, const void* B, void* C,
                               int Mo, int K, int mode, float alpha) {
    dim3 grid(M_ / 128, (Mo + 127) / 128);
    gemm_fp16<<<grid, 256>>>((const float*)A, (const float*)B, (float*)C,
                             Mo, M_, K, mode, alpha);
}

extern "C" void kernel_launch(void* const* d_in, const int* in_sizes, int n_in,
                              void* d_out, int out_size) {
    (void)in_sizes; (void)n_in; (void)out_size;
    const float* x         = (const float*)d_in[0];
    const float* support   = (const float*)d_in[1];  // [2,V,V] = concat k-major!
    const float* support_c = (const float*)d_in[2];  // [2,VC,VC]
    const float* acs       = (const float*)d_in[3];
    const float* afc       = (const float*)d_in[4];
    const float* W         = (const float*)d_in[5];
    const float* b         = (const float*)d_in[6];
    float* out = (float*)d_out;

    void *pX, *pZ23, *pHF, *pXc, *pZc23, *pHC;
    void *pSxg, *pZs23, *pHS, *psup01, *pacsT, *pafcT;
    cudaGetSymbolAddress(&pX, g_X);       cudaGetSymbolAddress(&pZ23, g_Z23);
    cudaGetSymbolAddress(&pHF, g_HF);     cudaGetSymbolAddress(&pXc, g_Xc);
    cudaGetSymbolAddress(&pZc23, g_Zc23); cudaGetSymbolAddress(&pHC, g_HC);
    cudaGetSymbolAddress(&pSxg, g_Sxg);   cudaGetSymbolAddress(&pZs23, g_Zs23);
    cudaGetSymbolAddress(&pHS, g_HS);     cudaGetSymbolAddress(&psup01, g_sup01);
    cudaGetSymbolAddress(&pacsT, g_acsT); cudaGetSymbolAddress(&pafcT, g_afcT);

    float* Z2  = (float*)pZ23;
    float* Z3  = Z2 + (size_t)V_ * M_;
    float* Zc2 = (float*)pZc23;
    float* Zc3 = Zc2 + (size_t)VC_ * M_;
    float* Zs2 = (float*)pZs23;
    float* Zs3 = Zs2 + (size_t)S_ * M_;

    // 1. layout transposes
    transpose_in<<<(N_ * C_ * V_ * L_ + 255) / 256, 256>>>(x);
    transpose_acs<<<(S_ * VC_ + 255) / 256, 256>>>(acs);
    transpose_afc<<<(VC_ * V_ + 255) / 256, 256>>>(afc);

    // 2. fine level: HF = b + W1 x; then one merged GEMM: HF += [A0;A1]^T [Z2;Z3]
    chanmix<<<V_, 192>>>((const float*)pX, W, b, (float*)pHF, Z2, Z3);
    launch_gemm(support, pZ23, pHF, V_, 2 * V_, 1, 1.f);

    // 3. coarse level
    launch_gemm(afc, pX, pXc, VC_, V_, 0, 1.f);
    chanmix<<<VC_, 192>>>((const float*)pXc, W, b, (float*)pHC, Zc2, Zc3);
    launch_gemm(support_c, pZc23, pHC, VC_, 2 * VC_, 1, 1.f);

    // 4. super level input
    launch_gemm(acs, pXc, pSxg, S_, VC_, 0, 1.f);

    // 5. data-dependent super supports (exact fp32)
    asmat_kernel<<<S_, 256>>>();
    supmat_kernel<<<1, 64>>>();

    // 6. super gcn (merged supports GEMM)
    chanmix<<<S_, 192>>>((const float*)pSxg, W, b, (float*)pHS, Zs2, Zs3);
    launch_gemm(psup01, pZs23, pHS, S_, 2 * S_, 1, 1.f);

    // 7. hierarchical residual fusions (order matters)
    launch_gemm(pacsT, pHS, pHC, VC_, S_,  2, N1F);
    launch_gemm(pafcT, pHC, pHF, V_,  VC_, 2, N2F);
    launch_gemm(afc,   pHF, pHC, VC_, V_,  2, N3F);
    launch_gemm(acs,   pHC, pHS, S_,  VC_, 2, N4F);

    // 8. write out
    transpose_out<<<(N_ * CO_ * (V_ + VC_ + S_) * L_ + 255) / 256, 256>>>(out);
}